// round 1
// baseline (speedup 1.0000x reference)
#include <cuda_runtime.h>

#define C 128
#define MAX_USERS   50000
#define MAX_ENT     50000
#define MAX_NODES  100000
#define MAX_E     1000000

// ---------------- scratch (allocation-free: __device__ globals) ----------------
__device__ float g_node_cur[(size_t)MAX_NODES * C];
__device__ float g_node_acc[(size_t)MAX_NODES * C];
__device__ float g_ent_cur [(size_t)MAX_ENT   * C];
__device__ float g_ent_acc [(size_t)MAX_ENT   * C];
__device__ float g_user_acc[(size_t)MAX_USERS * C];
__device__ float g_Q       [(size_t)MAX_NODES * C];
__device__ float g_K       [(size_t)MAX_NODES * C];
__device__ float g_exps    [(size_t)MAX_E * 2];
__device__ float g_z       [(size_t)MAX_NODES * 2];
__device__ float g_aug     [(size_t)MAX_E];
__device__ float g_cnt_node[MAX_NODES];
__device__ float g_cnt_ent [MAX_ENT];

// ---------------- helpers ----------------
__device__ __forceinline__ void red_add4(float* addr, float a, float b, float c, float d) {
    asm volatile("red.global.add.v4.f32 [%0], {%1,%2,%3,%4};"
                 :: "l"(addr), "f"(a), "f"(b), "f"(c), "f"(d) : "memory");
}
__device__ __forceinline__ void red_add1(float* addr, float a) {
    asm volatile("red.global.add.f32 [%0], %1;" :: "l"(addr), "f"(a) : "memory");
}

// ---------------- Q/K projection: out = node_emb @ W (both W_Q and W_K) ----------------
// blockDim = 512; ROWS=64 rows per block. smem: W_Q|W_K (128KB) + 64 rows (32KB).
// thread layout: lane = col-group (4 cols), wid = t>>5; mat = wid&1; rowgroup = wid>>1 (8 rows).
__global__ __launch_bounds__(512) void qk_gemm(
    const float* __restrict__ node, const float* __restrict__ WQ,
    const float* __restrict__ WK, float* __restrict__ Q, float* __restrict__ K, int n)
{
    extern __shared__ float sm[];
    float* sW = sm;              // [2][128][128]
    float* sR = sm + 32768;      // [64][128]
    int t = threadIdx.x;
    int row0 = blockIdx.x * 64;

    for (int i = t; i < 8192; i += 512) {
        ((float4*)sW)[i] = (i < 4096) ? ((const float4*)WQ)[i]
                                      : ((const float4*)WK)[i - 4096];
    }
    for (int i = t; i < 2048; i += 512) {
        int r = i >> 5, c = i & 31;
        int gr = row0 + r;
        float4 v = make_float4(0.f, 0.f, 0.f, 0.f);
        if (gr < n) v = ((const float4*)(node + (size_t)gr * C))[c];
        ((float4*)sR)[i] = v;
    }
    __syncthreads();

    int lane = t & 31;          // output column group: cols lane*4 .. lane*4+3
    int wid  = t >> 5;
    int mat  = wid & 1;         // 0 = Q, 1 = K
    int rg   = wid >> 1;        // 0..7 -> rows rg*8 .. rg*8+7
    const float* wbase = sW + mat * 16384 + lane * 4;
    const float* rbase = sR + rg * 8 * C;

    float acc[8][4];
#pragma unroll
    for (int r = 0; r < 8; r++)
#pragma unroll
        for (int c = 0; c < 4; c++) acc[r][c] = 0.f;

#pragma unroll 4
    for (int k = 0; k < 128; k += 4) {
        float4 w0 = *(const float4*)(wbase + (k + 0) * C);
        float4 w1 = *(const float4*)(wbase + (k + 1) * C);
        float4 w2 = *(const float4*)(wbase + (k + 2) * C);
        float4 w3 = *(const float4*)(wbase + (k + 3) * C);
#pragma unroll
        for (int r = 0; r < 8; r++) {
            float4 rv = *(const float4*)(rbase + r * C + k);
            acc[r][0] += rv.x * w0.x + rv.y * w1.x + rv.z * w2.x + rv.w * w3.x;
            acc[r][1] += rv.x * w0.y + rv.y * w1.y + rv.z * w2.y + rv.w * w3.y;
            acc[r][2] += rv.x * w0.z + rv.y * w1.z + rv.z * w2.z + rv.w * w3.z;
            acc[r][3] += rv.x * w0.w + rv.y * w1.w + rv.z * w2.w + rv.w * w3.w;
        }
    }

    float* outb = mat ? K : Q;
#pragma unroll
    for (int r = 0; r < 8; r++) {
        int gr = row0 + rg * 8 + r;
        if (gr < n) {
            float4 o = make_float4(acc[r][0], acc[r][1], acc[r][2], acc[r][3]);
            ((float4*)(outb + (size_t)gr * C))[lane] = o;
        }
    }
}

// ---------------- attention: per-edge 2-head dot product, exp, segment-sum z ----------------
__global__ __launch_bounds__(256) void attn_score(
    const int* __restrict__ head, const int* __restrict__ tail,
    const float* __restrict__ Q, const float* __restrict__ K,
    float* __restrict__ exps, float* __restrict__ z, int E)
{
    int gw = (blockIdx.x * 256 + threadIdx.x) >> 5;
    int lane = threadIdx.x & 31;
    if (gw >= E) return;
    int h = __ldg(head + gw), t = __ldg(tail + gw);
    float4 q = *(const float4*)(Q + (size_t)h * C + lane * 4);
    float4 k = *(const float4*)(K + (size_t)t * C + lane * 4);
    float p = q.x * k.x + q.y * k.y + q.z * k.z + q.w * k.w;
    // reduce within 16-lane halves: lanes 0-15 = head 0, 16-31 = head 1
    p += __shfl_xor_sync(0xffffffffu, p, 8);
    p += __shfl_xor_sync(0xffffffffu, p, 4);
    p += __shfl_xor_sync(0xffffffffu, p, 2);
    p += __shfl_xor_sync(0xffffffffu, p, 1);
    if ((lane & 15) == 0) {
        int hh = lane >> 4;
        float ex = expf(p * 0.125f);   // / sqrt(64)
        exps[(size_t)gw * 2 + hh] = ex;
        red_add1(z + (size_t)h * 2 + hh, ex);
    }
}

__global__ __launch_bounds__(256) void attn_aug(
    const int* __restrict__ head, const float* __restrict__ exps,
    const float* __restrict__ z, float* __restrict__ aug, int E)
{
    int e = blockIdx.x * 256 + threadIdx.x;
    if (e >= E) return;
    int h = __ldg(head + e);
    float a0 = exps[(size_t)e * 2 + 0] / z[(size_t)h * 2 + 0];
    float a1 = exps[(size_t)e * 2 + 1] / z[(size_t)h * 2 + 1];
    aug[e] = 0.5f * (a0 + a1);
}

// ---------------- edge aggregations (warp per edge) ----------------
__global__ __launch_bounds__(256) void ent_agg(
    const int* __restrict__ head, const int* __restrict__ tail,
    const int* __restrict__ etype, const float* __restrict__ src,
    const float* __restrict__ weight, float* acc, float* cnt, int E)
{
    int gw = (blockIdx.x * 256 + threadIdx.x) >> 5;
    int lane = threadIdx.x & 31;
    if (gw >= E) return;
    int h = __ldg(head + gw), t = __ldg(tail + gw), r = __ldg(etype + gw) - 1;
    float4 s = *(const float4*)(src + (size_t)t * C + lane * 4);
    float4 w = *(const float4*)(weight + (size_t)r * C + lane * 4);
    red_add4(acc + (size_t)h * C + lane * 4, s.x * w.x, s.y * w.y, s.z * w.z, s.w * w.w);
    if (lane == 0) red_add1(cnt + h, 1.0f);
}

__global__ __launch_bounds__(256) void node_agg(
    const int* __restrict__ head, const int* __restrict__ tail,
    const float* __restrict__ aug, const float* __restrict__ src,
    float* acc, float* cnt, int E)
{
    int gw = (blockIdx.x * 256 + threadIdx.x) >> 5;
    int lane = threadIdx.x & 31;
    if (gw >= E) return;
    int h = __ldg(head + gw), t = __ldg(tail + gw);
    float a = __ldg(aug + gw);
    float4 s = *(const float4*)(src + (size_t)t * C + lane * 4);
    red_add4(acc + (size_t)h * C + lane * 4, s.x * a, s.y * a, s.z * a, s.w * a);
    if (lane == 0) red_add1(cnt + h, 1.0f);
}

__global__ __launch_bounds__(256) void user_agg(
    const int* __restrict__ rows, const int* __restrict__ cols,
    const float* __restrict__ vals, const float* __restrict__ ent,
    float* acc, int E)
{
    int gw = (blockIdx.x * 256 + threadIdx.x) >> 5;
    int lane = threadIdx.x & 31;
    if (gw >= E) return;
    int r = __ldg(rows + gw), c = __ldg(cols + gw);
    float v = __ldg(vals + gw);
    float4 s = *(const float4*)(ent + (size_t)c * C + lane * 4);
    red_add4(acc + (size_t)r * C + lane * 4, s.x * v, s.y * v, s.z * v, s.w * v);
}

// ---------------- elementwise: divide by counts (scatter-mean) ----------------
__global__ __launch_bounds__(256) void div_cnt(float* acc, const float* __restrict__ cnt, int n)
{
    int i = blockIdx.x * 256 + threadIdx.x;   // one float4 per thread
    if (i >= n * 32) return;
    int row = i >> 5;
    float inv = 1.0f / fmaxf(__ldg(cnt + row), 1.0f);
    float4 v = ((float4*)acc)[i];
    v.x *= inv; v.y *= inv; v.z *= inv; v.w *= inv;
    ((float4*)acc)[i] = v;
}

// ---------------- l2-normalize (warp per row) + accumulate into residual ----------------
__global__ __launch_bounds__(256) void norm_res(
    const float* __restrict__ in, float* cur, float* res, int n)
{
    int gw = (blockIdx.x * 256 + threadIdx.x) >> 5;
    int lane = threadIdx.x & 31;
    if (gw >= n) return;
    float4 v = ((const float4*)(in + (size_t)gw * C))[lane];
    float ss = v.x * v.x + v.y * v.y + v.z * v.z + v.w * v.w;
    ss += __shfl_xor_sync(0xffffffffu, ss, 16);
    ss += __shfl_xor_sync(0xffffffffu, ss, 8);
    ss += __shfl_xor_sync(0xffffffffu, ss, 4);
    ss += __shfl_xor_sync(0xffffffffu, ss, 2);
    ss += __shfl_xor_sync(0xffffffffu, ss, 1);
    float inv = 1.0f / fmaxf(sqrtf(ss), 1e-12f);
    float4 o = make_float4(v.x * inv, v.y * inv, v.z * inv, v.w * inv);
    if (cur) ((float4*)(cur + (size_t)gw * C))[lane] = o;
    float4 r = ((float4*)(res + (size_t)gw * C))[lane];
    r.x += o.x; r.y += o.y; r.z += o.z; r.w += o.w;
    ((float4*)(res + (size_t)gw * C))[lane] = r;
}

// ---------------- host launcher ----------------
extern "C" void kernel_launch(void* const* d_in, const int* in_sizes, int n_in,
                              void* d_out, int out_size)
{
    const float* user   = (const float*)d_in[0];
    const float* ent    = (const float*)d_in[1];
    const int*   eidx   = (const int*)  d_in[2];
    const int*   etype  = (const int*)  d_in[3];
    const int*   exidx  = (const int*)  d_in[4];
    // d_in[5] extra_edge_type: unused by reference
    const int*   irows  = (const int*)  d_in[6];
    const int*   icols  = (const int*)  d_in[7];
    const float* ivals  = (const float*)d_in[8];
    const float* weight = (const float*)d_in[9];
    // d_in[10] extra_weight: unused by reference
    const float* WQ     = (const float*)d_in[11];
    const float* WK     = (const float*)d_in[12];

    int n_users = in_sizes[0] / C;
    int n_ent   = in_sizes[1] / C;
    int n_nodes = n_users + n_ent;
    int E   = in_sizes[3];
    int EX  = in_sizes[5];
    int NNZ = in_sizes[6];

    size_t UB = (size_t)n_users * C;
    size_t EB = (size_t)n_ent * C;
    size_t NB = (size_t)n_nodes * C;

    float *node_cur, *node_acc, *ent_cur, *ent_acc, *user_acc;
    float *Q, *K, *exps, *z, *aug, *cn, *ce;
    cudaGetSymbolAddress((void**)&node_cur, g_node_cur);
    cudaGetSymbolAddress((void**)&node_acc, g_node_acc);
    cudaGetSymbolAddress((void**)&ent_cur,  g_ent_cur);
    cudaGetSymbolAddress((void**)&ent_acc,  g_ent_acc);
    cudaGetSymbolAddress((void**)&user_acc, g_user_acc);
    cudaGetSymbolAddress((void**)&Q,        g_Q);
    cudaGetSymbolAddress((void**)&K,        g_K);
    cudaGetSymbolAddress((void**)&exps,     g_exps);
    cudaGetSymbolAddress((void**)&z,        g_z);
    cudaGetSymbolAddress((void**)&aug,      g_aug);
    cudaGetSymbolAddress((void**)&cn,       g_cnt_node);
    cudaGetSymbolAddress((void**)&ce,       g_cnt_ent);

    float* out = (float*)d_out;
    float* user_res = out;              // [n_users, C]
    float* ent_res  = out + UB;         // [n_ent, C]
    float* node_res = out + UB + EB;    // [n_nodes, C]

    // init working state + residuals
    cudaMemcpyAsync(node_cur,      user, UB * 4, cudaMemcpyDeviceToDevice);
    cudaMemcpyAsync(node_cur + UB, ent,  EB * 4, cudaMemcpyDeviceToDevice);
    cudaMemcpyAsync(ent_cur,       ent,  EB * 4, cudaMemcpyDeviceToDevice);
    cudaMemcpyAsync(user_res,      user, UB * 4, cudaMemcpyDeviceToDevice);
    cudaMemcpyAsync(ent_res,       ent,  EB * 4, cudaMemcpyDeviceToDevice);
    cudaMemcpyAsync(node_res,      user, UB * 4, cudaMemcpyDeviceToDevice);
    cudaMemcpyAsync(node_res + UB, ent,  EB * 4, cudaMemcpyDeviceToDevice);

    // Q/K projections on the original node embedding
    cudaFuncSetAttribute(qk_gemm, cudaFuncAttributeMaxDynamicSharedMemorySize, 163840);
    qk_gemm<<<(n_nodes + 63) / 64, 512, 163840>>>(node_cur, WQ, WK, Q, K, n_nodes);

    // attention edge weights on the extra (preference) graph
    const int* xh = exidx;
    const int* xt = exidx + EX;
    cudaMemsetAsync(z, 0, (size_t)n_nodes * 2 * 4);
    attn_score<<<(EX * 32 + 255) / 256, 256>>>(xh, xt, Q, K, exps, z, EX);
    attn_aug  <<<(EX + 255) / 256, 256>>>(xh, exps, z, aug, EX);

    const int* eh = eidx;
    const int* et = eidx + E;

    for (int hop = 0; hop < 2; hop++) {
        // entity KG scatter-mean
        cudaMemsetAsync(ent_acc, 0, EB * 4);
        cudaMemsetAsync(ce, 0, (size_t)n_ent * 4);
        ent_agg<<<(E * 32 + 255) / 256, 256>>>(eh, et, etype, ent_cur, weight, ent_acc, ce, E);

        // preference-graph scatter-mean
        cudaMemsetAsync(node_acc, 0, NB * 4);
        cudaMemsetAsync(cn, 0, (size_t)n_nodes * 4);
        node_agg<<<(EX * 32 + 255) / 256, 256>>>(xh, xt, aug, node_cur, node_acc, cn, EX);

        // finalize entity mean (pre-l2norm value feeds the interact matmul)
        div_cnt<<<(n_ent * 32 + 255) / 256, 256>>>(ent_acc, ce, n_ent);

        // user = interact_mat @ entity_new
        cudaMemsetAsync(user_acc, 0, UB * 4);
        user_agg<<<(NNZ * 32 + 255) / 256, 256>>>(irows, icols, ivals, ent_acc, user_acc, NNZ);

        // finalize node mean
        div_cnt<<<(n_nodes * 32 + 255) / 256, 256>>>(node_acc, cn, n_nodes);

        // l2norm + residual accumulation
        norm_res<<<(n_ent   * 32 + 255) / 256, 256>>>(ent_acc,  ent_cur,  ent_res,  n_ent);
        norm_res<<<(n_nodes * 32 + 255) / 256, 256>>>(node_acc, node_cur, node_res, n_nodes);
        norm_res<<<(n_users * 32 + 255) / 256, 256>>>(user_acc, (float*)0, user_res, n_users);
    }
}

// round 2
// speedup vs baseline: 1.8468x; 1.8468x over previous
#include <cuda_runtime.h>

#define C 128
#define MAX_USERS   50000
#define MAX_ENT     50000
#define MAX_NODES  100000
#define MAX_E     1000000

// ---------------- scratch (allocation-free: __device__ globals) ----------------
__device__ float g_nodeA  [(size_t)MAX_NODES * C];
__device__ float g_nodeB  [(size_t)MAX_NODES * C];
__device__ float g_entB   [(size_t)MAX_ENT   * C];
__device__ float g_entMean[(size_t)MAX_ENT   * C];
__device__ float g_Q      [(size_t)MAX_NODES * C];
__device__ float g_K      [(size_t)MAX_NODES * C];
__device__ int    g_srt_ent[MAX_E];
__device__ int    g_srt_x  [MAX_E];
__device__ int2   g_srt_i  [MAX_E];
__device__ float2 g_exps   [MAX_E];
__device__ float  g_aug    [MAX_E];
__device__ int g_off_e[MAX_ENT + 1];
__device__ int g_off_n[MAX_NODES + 1];
__device__ int g_off_u[MAX_USERS + 1];
__device__ int g_deg   [MAX_NODES];
__device__ int g_cursor[MAX_NODES];
__device__ int g_part  [256];

// ================= CSR build =================
__global__ __launch_bounds__(256) void hist_k(const int* __restrict__ head, int* __restrict__ deg, int E)
{
    int i = blockIdx.x * 256 + threadIdx.x;
    if (i < E) atomicAdd(deg + __ldg(head + i), 1);
}

__global__ __launch_bounds__(1024) void scan_block(const int* __restrict__ deg,
                                                   int* __restrict__ off, int* __restrict__ part, int n)
{
    __shared__ int ws[32];
    int t = threadIdx.x;
    int gid = blockIdx.x * 1024 + t;
    int v = (gid < n) ? deg[gid] : 0;
    int x = v;
#pragma unroll
    for (int d = 1; d < 32; d <<= 1) {
        int y = __shfl_up_sync(0xffffffffu, x, d);
        if ((t & 31) >= d) x += y;
    }
    if ((t & 31) == 31) ws[t >> 5] = x;
    __syncthreads();
    if (t < 32) {
        int s = ws[t];
#pragma unroll
        for (int d = 1; d < 32; d <<= 1) {
            int y = __shfl_up_sync(0xffffffffu, s, d);
            if (t >= d) s += y;
        }
        ws[t] = s;
    }
    __syncthreads();
    int excl = x - v + ((t >= 32) ? ws[(t >> 5) - 1] : 0);
    if (gid < n) off[gid] = excl;
    if (t == 1023) part[blockIdx.x] = excl + v;
}

// single warp scans up to 128 partials; part[nb] = total
__global__ void scan_part(int* part, int nb)
{
    int t = threadIdx.x;   // 32 threads
    int v[4];
#pragma unroll
    for (int i = 0; i < 4; i++) { int idx = t * 4 + i; v[i] = (idx < nb) ? part[idx] : 0; }
    int loc = v[0] + v[1] + v[2] + v[3];
    int x = loc;
#pragma unroll
    for (int d = 1; d < 32; d <<= 1) {
        int y = __shfl_up_sync(0xffffffffu, x, d);
        if (t >= d) x += y;
    }
    int excl = x - loc;
#pragma unroll
    for (int i = 0; i < 4; i++) { int idx = t * 4 + i; if (idx < nb) part[idx] = excl; excl += v[i]; }
    if (t == 31) part[nb] = x;
}

__global__ __launch_bounds__(256) void add_offs(int* __restrict__ off, const int* __restrict__ part, int n)
{
    int i = blockIdx.x * 256 + threadIdx.x;
    if (i < n) off[i] += part[i >> 10];
    else if (i == n) off[i] = part[(n + 1023) >> 10];
}

__global__ __launch_bounds__(256) void scat_ent(const int* __restrict__ h, const int* __restrict__ t,
                                                const int* __restrict__ ty, int* __restrict__ cur,
                                                int* __restrict__ srt, int E)
{
    int e = blockIdx.x * 256 + threadIdx.x;
    if (e >= E) return;
    int p = atomicAdd(cur + __ldg(h + e), 1);
    srt[p] = __ldg(t + e) | ((__ldg(ty + e) - 1) << 16);
}

__global__ __launch_bounds__(256) void scat_x(const int* __restrict__ h, const int* __restrict__ t,
                                              int* __restrict__ cur, int* __restrict__ srt, int E)
{
    int e = blockIdx.x * 256 + threadIdx.x;
    if (e >= E) return;
    int p = atomicAdd(cur + __ldg(h + e), 1);
    srt[p] = __ldg(t + e);
}

__global__ __launch_bounds__(256) void scat_i(const int* __restrict__ r, const int* __restrict__ c,
                                              const float* __restrict__ v, int* __restrict__ cur,
                                              int2* __restrict__ srt, int E)
{
    int e = blockIdx.x * 256 + threadIdx.x;
    if (e >= E) return;
    int p = atomicAdd(cur + __ldg(r + e), 1);
    srt[p] = make_int2(__ldg(c + e), __float_as_int(__ldg(v + e)));
}

// ================= Q/K projection (dense, smem-tiled) =================
__global__ __launch_bounds__(512) void qk_gemm(
    const float* __restrict__ node, const float* __restrict__ WQ,
    const float* __restrict__ WK, float* __restrict__ Q, float* __restrict__ K, int n)
{
    extern __shared__ float sm[];
    float* sW = sm;              // [2][128][128]
    float* sR = sm + 32768;      // [64][128]
    int t = threadIdx.x;
    int row0 = blockIdx.x * 64;

    for (int i = t; i < 8192; i += 512) {
        ((float4*)sW)[i] = (i < 4096) ? ((const float4*)WQ)[i]
                                      : ((const float4*)WK)[i - 4096];
    }
    for (int i = t; i < 2048; i += 512) {
        int r = i >> 5, c = i & 31;
        int gr = row0 + r;
        float4 v = make_float4(0.f, 0.f, 0.f, 0.f);
        if (gr < n) v = ((const float4*)(node + (size_t)gr * C))[c];
        ((float4*)sR)[i] = v;
    }
    __syncthreads();

    int lane = t & 31;
    int wid  = t >> 5;
    int mat  = wid & 1;
    int rg   = wid >> 1;
    const float* wbase = sW + mat * 16384 + lane * 4;
    const float* rbase = sR + rg * 8 * C;

    float acc[8][4];
#pragma unroll
    for (int r = 0; r < 8; r++)
#pragma unroll
        for (int c = 0; c < 4; c++) acc[r][c] = 0.f;

#pragma unroll 4
    for (int k = 0; k < 128; k += 4) {
        float4 w0 = *(const float4*)(wbase + (k + 0) * C);
        float4 w1 = *(const float4*)(wbase + (k + 1) * C);
        float4 w2 = *(const float4*)(wbase + (k + 2) * C);
        float4 w3 = *(const float4*)(wbase + (k + 3) * C);
#pragma unroll
        for (int r = 0; r < 8; r++) {
            float4 rv = *(const float4*)(rbase + r * C + k);
            acc[r][0] += rv.x * w0.x + rv.y * w1.x + rv.z * w2.x + rv.w * w3.x;
            acc[r][1] += rv.x * w0.y + rv.y * w1.y + rv.z * w2.y + rv.w * w3.y;
            acc[r][2] += rv.x * w0.z + rv.y * w1.z + rv.z * w2.z + rv.w * w3.z;
            acc[r][3] += rv.x * w0.w + rv.y * w1.w + rv.z * w2.w + rv.w * w3.w;
        }
    }

    float* outb = mat ? K : Q;
#pragma unroll
    for (int r = 0; r < 8; r++) {
        int gr = row0 + rg * 8 + r;
        if (gr < n) {
            float4 o = make_float4(acc[r][0], acc[r][1], acc[r][2], acc[r][3]);
            ((float4*)(outb + (size_t)gr * C))[lane] = o;
        }
    }
}

// ================= fused attention (CSR): score, exp, row-z, aug =================
__global__ __launch_bounds__(256) void attn_csr(
    const int* __restrict__ off, const int* __restrict__ srt,
    const float* __restrict__ Q, const float* __restrict__ K,
    float2* __restrict__ exps, float* __restrict__ aug, int n)
{
    int gw = (blockIdx.x * 256 + threadIdx.x) >> 5, lane = threadIdx.x & 31;
    if (gw >= n) return;
    int base = off[gw], end = off[gw + 1];
    if (base == end) return;
    float4 q = __ldg((const float4*)(Q + (size_t)gw * C) + lane);
    float z0 = 0.f, z1 = 0.f;
    for (int e0 = base; e0 < end; e0 += 32) {
        int cnt = min(32, end - e0);
        int meta = (lane < cnt) ? __ldg(srt + e0 + lane) : 0;
        float my0 = 0.f, my1 = 0.f;
        for (int j = 0; j < cnt; j++) {
            int tl = __shfl_sync(0xffffffffu, meta, j);
            float4 k4 = __ldg((const float4*)(K + (size_t)tl * C) + lane);
            float p = q.x * k4.x + q.y * k4.y + q.z * k4.z + q.w * k4.w;
            p += __shfl_xor_sync(0xffffffffu, p, 8);
            p += __shfl_xor_sync(0xffffffffu, p, 4);
            p += __shfl_xor_sync(0xffffffffu, p, 2);
            p += __shfl_xor_sync(0xffffffffu, p, 1);
            float po = __shfl_xor_sync(0xffffffffu, p, 16);
            float s0 = (lane < 16) ? p : po;
            float s1 = (lane < 16) ? po : p;
            float ex0 = __expf(s0 * 0.125f);
            float ex1 = __expf(s1 * 0.125f);
            z0 += ex0; z1 += ex1;
            if (lane == j) { my0 = ex0; my1 = ex1; }
        }
        if (lane < cnt) exps[e0 + lane] = make_float2(my0, my1);
    }
    float iz0 = 0.5f / z0, iz1 = 0.5f / z1;
    for (int e0 = base; e0 < end; e0 += 32) {
        int cnt = min(32, end - e0);
        if (lane < cnt) {
            float2 ex = exps[e0 + lane];
            aug[e0 + lane] = ex.x * iz0 + ex.y * iz1;
        }
    }
}

// ================= entity KG aggregation (CSR, fused mean+norm+res) =================
__global__ __launch_bounds__(256) void ent_agg_csr(
    const int* __restrict__ off, const int* __restrict__ srt,
    const float* __restrict__ src, const float* __restrict__ wgt,
    float* __restrict__ mean_out, float* __restrict__ cur_out,
    float* __restrict__ res, const float* __restrict__ res_init, int n)
{
    __shared__ float sW[15 * C];
    for (int i = threadIdx.x; i < 15 * C; i += 256) sW[i] = wgt[i];
    __syncthreads();
    int gw = (blockIdx.x * 256 + threadIdx.x) >> 5, lane = threadIdx.x & 31;
    if (gw >= n) return;
    int base = off[gw], end = off[gw + 1];
    float4 acc = make_float4(0.f, 0.f, 0.f, 0.f);
    for (int e0 = base; e0 < end; e0 += 32) {
        int cnt = min(32, end - e0);
        int meta = (lane < cnt) ? __ldg(srt + e0 + lane) : 0;
        int j = 0;
        for (; j + 4 <= cnt; j += 4) {
            int m0 = __shfl_sync(0xffffffffu, meta, j + 0);
            int m1 = __shfl_sync(0xffffffffu, meta, j + 1);
            int m2 = __shfl_sync(0xffffffffu, meta, j + 2);
            int m3 = __shfl_sync(0xffffffffu, meta, j + 3);
            float4 v0 = __ldg((const float4*)(src + (size_t)(m0 & 0xFFFF) * C) + lane);
            float4 v1 = __ldg((const float4*)(src + (size_t)(m1 & 0xFFFF) * C) + lane);
            float4 v2 = __ldg((const float4*)(src + (size_t)(m2 & 0xFFFF) * C) + lane);
            float4 v3 = __ldg((const float4*)(src + (size_t)(m3 & 0xFFFF) * C) + lane);
            float4 w0 = *((const float4*)(sW + (((unsigned)m0) >> 16) * C) + lane);
            float4 w1 = *((const float4*)(sW + (((unsigned)m1) >> 16) * C) + lane);
            float4 w2 = *((const float4*)(sW + (((unsigned)m2) >> 16) * C) + lane);
            float4 w3 = *((const float4*)(sW + (((unsigned)m3) >> 16) * C) + lane);
            acc.x += v0.x * w0.x + v1.x * w1.x + v2.x * w2.x + v3.x * w3.x;
            acc.y += v0.y * w0.y + v1.y * w1.y + v2.y * w2.y + v3.y * w3.y;
            acc.z += v0.z * w0.z + v1.z * w1.z + v2.z * w2.z + v3.z * w3.z;
            acc.w += v0.w * w0.w + v1.w * w1.w + v2.w * w2.w + v3.w * w3.w;
        }
        for (; j < cnt; j++) {
            int m0 = __shfl_sync(0xffffffffu, meta, j);
            float4 v0 = __ldg((const float4*)(src + (size_t)(m0 & 0xFFFF) * C) + lane);
            float4 w0 = *((const float4*)(sW + (((unsigned)m0) >> 16) * C) + lane);
            acc.x += v0.x * w0.x; acc.y += v0.y * w0.y;
            acc.z += v0.z * w0.z; acc.w += v0.w * w0.w;
        }
    }
    float inv = 1.0f / fmaxf((float)(end - base), 1.0f);
    float4 m = make_float4(acc.x * inv, acc.y * inv, acc.z * inv, acc.w * inv);
    ((float4*)(mean_out + (size_t)gw * C))[lane] = m;
    float ss = m.x * m.x + m.y * m.y + m.z * m.z + m.w * m.w;
    ss += __shfl_xor_sync(0xffffffffu, ss, 16);
    ss += __shfl_xor_sync(0xffffffffu, ss, 8);
    ss += __shfl_xor_sync(0xffffffffu, ss, 4);
    ss += __shfl_xor_sync(0xffffffffu, ss, 2);
    ss += __shfl_xor_sync(0xffffffffu, ss, 1);
    float ni = 1.0f / fmaxf(sqrtf(ss), 1e-12f);
    float4 o = make_float4(m.x * ni, m.y * ni, m.z * ni, m.w * ni);
    if (cur_out) ((float4*)(cur_out + (size_t)gw * C))[lane] = o;
    float4 r = __ldg((const float4*)(res_init + (size_t)gw * C) + lane);
    r.x += o.x; r.y += o.y; r.z += o.z; r.w += o.w;
    ((float4*)(res + (size_t)gw * C))[lane] = r;
}

// ================= preference-graph aggregation (CSR, fused norm+res) =================
__global__ __launch_bounds__(256) void node_agg_csr(
    const int* __restrict__ off, const int* __restrict__ srt,
    const float* __restrict__ aug, const float* __restrict__ src,
    float* __restrict__ cur_out, float* __restrict__ res,
    const float* __restrict__ res_init, int n)
{
    int gw = (blockIdx.x * 256 + threadIdx.x) >> 5, lane = threadIdx.x & 31;
    if (gw >= n) return;
    int base = off[gw], end = off[gw + 1];
    float4 acc = make_float4(0.f, 0.f, 0.f, 0.f);
    for (int e0 = base; e0 < end; e0 += 32) {
        int cnt = min(32, end - e0);
        int meta = 0; float av = 0.f;
        if (lane < cnt) { meta = __ldg(srt + e0 + lane); av = __ldg(aug + e0 + lane); }
        int j = 0;
        for (; j + 4 <= cnt; j += 4) {
            int m0 = __shfl_sync(0xffffffffu, meta, j + 0);
            int m1 = __shfl_sync(0xffffffffu, meta, j + 1);
            int m2 = __shfl_sync(0xffffffffu, meta, j + 2);
            int m3 = __shfl_sync(0xffffffffu, meta, j + 3);
            float a0 = __shfl_sync(0xffffffffu, av, j + 0);
            float a1 = __shfl_sync(0xffffffffu, av, j + 1);
            float a2 = __shfl_sync(0xffffffffu, av, j + 2);
            float a3 = __shfl_sync(0xffffffffu, av, j + 3);
            float4 v0 = __ldg((const float4*)(src + (size_t)m0 * C) + lane);
            float4 v1 = __ldg((const float4*)(src + (size_t)m1 * C) + lane);
            float4 v2 = __ldg((const float4*)(src + (size_t)m2 * C) + lane);
            float4 v3 = __ldg((const float4*)(src + (size_t)m3 * C) + lane);
            acc.x += v0.x * a0 + v1.x * a1 + v2.x * a2 + v3.x * a3;
            acc.y += v0.y * a0 + v1.y * a1 + v2.y * a2 + v3.y * a3;
            acc.z += v0.z * a0 + v1.z * a1 + v2.z * a2 + v3.z * a3;
            acc.w += v0.w * a0 + v1.w * a1 + v2.w * a2 + v3.w * a3;
        }
        for (; j < cnt; j++) {
            int m0 = __shfl_sync(0xffffffffu, meta, j);
            float a0 = __shfl_sync(0xffffffffu, av, j);
            float4 v0 = __ldg((const float4*)(src + (size_t)m0 * C) + lane);
            acc.x += v0.x * a0; acc.y += v0.y * a0;
            acc.z += v0.z * a0; acc.w += v0.w * a0;
        }
    }
    // l2norm is scale-invariant: normalize the raw sum (mean division skipped)
    float ss = acc.x * acc.x + acc.y * acc.y + acc.z * acc.z + acc.w * acc.w;
    ss += __shfl_xor_sync(0xffffffffu, ss, 16);
    ss += __shfl_xor_sync(0xffffffffu, ss, 8);
    ss += __shfl_xor_sync(0xffffffffu, ss, 4);
    ss += __shfl_xor_sync(0xffffffffu, ss, 2);
    ss += __shfl_xor_sync(0xffffffffu, ss, 1);
    float ni = 1.0f / fmaxf(sqrtf(ss), 1e-12f);
    float4 o = make_float4(acc.x * ni, acc.y * ni, acc.z * ni, acc.w * ni);
    if (cur_out) ((float4*)(cur_out + (size_t)gw * C))[lane] = o;
    float4 r = __ldg((const float4*)(res_init + (size_t)gw * C) + lane);
    r.x += o.x; r.y += o.y; r.z += o.z; r.w += o.w;
    ((float4*)(res + (size_t)gw * C))[lane] = r;
}

// ================= interact-mat aggregation (CSR, fused norm+res) =================
__global__ __launch_bounds__(256) void user_agg_csr(
    const int* __restrict__ off, const int2* __restrict__ srt,
    const float* __restrict__ src, float* __restrict__ res,
    const float* __restrict__ res_init, int n)
{
    int gw = (blockIdx.x * 256 + threadIdx.x) >> 5, lane = threadIdx.x & 31;
    if (gw >= n) return;
    int base = off[gw], end = off[gw + 1];
    float4 acc = make_float4(0.f, 0.f, 0.f, 0.f);
    for (int e0 = base; e0 < end; e0 += 32) {
        int cnt = min(32, end - e0);
        int mc = 0; float mv = 0.f;
        if (lane < cnt) { int2 p = __ldg(srt + e0 + lane); mc = p.x; mv = __int_as_float(p.y); }
        int j = 0;
        for (; j + 4 <= cnt; j += 4) {
            int c0 = __shfl_sync(0xffffffffu, mc, j + 0);
            int c1 = __shfl_sync(0xffffffffu, mc, j + 1);
            int c2 = __shfl_sync(0xffffffffu, mc, j + 2);
            int c3 = __shfl_sync(0xffffffffu, mc, j + 3);
            float a0 = __shfl_sync(0xffffffffu, mv, j + 0);
            float a1 = __shfl_sync(0xffffffffu, mv, j + 1);
            float a2 = __shfl_sync(0xffffffffu, mv, j + 2);
            float a3 = __shfl_sync(0xffffffffu, mv, j + 3);
            float4 v0 = __ldg((const float4*)(src + (size_t)c0 * C) + lane);
            float4 v1 = __ldg((const float4*)(src + (size_t)c1 * C) + lane);
            float4 v2 = __ldg((const float4*)(src + (size_t)c2 * C) + lane);
            float4 v3 = __ldg((const float4*)(src + (size_t)c3 * C) + lane);
            acc.x += v0.x * a0 + v1.x * a1 + v2.x * a2 + v3.x * a3;
            acc.y += v0.y * a0 + v1.y * a1 + v2.y * a2 + v3.y * a3;
            acc.z += v0.z * a0 + v1.z * a1 + v2.z * a2 + v3.z * a3;
            acc.w += v0.w * a0 + v1.w * a1 + v2.w * a2 + v3.w * a3;
        }
        for (; j < cnt; j++) {
            int c0 = __shfl_sync(0xffffffffu, mc, j);
            float a0 = __shfl_sync(0xffffffffu, mv, j);
            float4 v0 = __ldg((const float4*)(src + (size_t)c0 * C) + lane);
            acc.x += v0.x * a0; acc.y += v0.y * a0;
            acc.z += v0.z * a0; acc.w += v0.w * a0;
        }
    }
    float ss = acc.x * acc.x + acc.y * acc.y + acc.z * acc.z + acc.w * acc.w;
    ss += __shfl_xor_sync(0xffffffffu, ss, 16);
    ss += __shfl_xor_sync(0xffffffffu, ss, 8);
    ss += __shfl_xor_sync(0xffffffffu, ss, 4);
    ss += __shfl_xor_sync(0xffffffffu, ss, 2);
    ss += __shfl_xor_sync(0xffffffffu, ss, 1);
    float ni = 1.0f / fmaxf(sqrtf(ss), 1e-12f);
    float4 o = make_float4(acc.x * ni, acc.y * ni, acc.z * ni, acc.w * ni);
    float4 r = __ldg((const float4*)(res_init + (size_t)gw * C) + lane);
    r.x += o.x; r.y += o.y; r.z += o.z; r.w += o.w;
    ((float4*)(res + (size_t)gw * C))[lane] = r;
}

// ================= host launcher =================
extern "C" void kernel_launch(void* const* d_in, const int* in_sizes, int n_in,
                              void* d_out, int out_size)
{
    const float* user   = (const float*)d_in[0];
    const float* ent    = (const float*)d_in[1];
    const int*   eidx   = (const int*)  d_in[2];
    const int*   etype  = (const int*)  d_in[3];
    const int*   exidx  = (const int*)  d_in[4];
    const int*   irows  = (const int*)  d_in[6];
    const int*   icols  = (const int*)  d_in[7];
    const float* ivals  = (const float*)d_in[8];
    const float* weight = (const float*)d_in[9];
    const float* WQ     = (const float*)d_in[11];
    const float* WK     = (const float*)d_in[12];

    int n_users = in_sizes[0] / C;
    int n_ent   = in_sizes[1] / C;
    int n_nodes = n_users + n_ent;
    int E   = in_sizes[3];
    int EX  = in_sizes[5];
    int NNZ = in_sizes[6];

    size_t UB = (size_t)n_users * C;
    size_t EB = (size_t)n_ent * C;

    float *nodeA, *nodeB, *entB, *entMean, *Q, *K, *augp;
    float2* exps;
    int *srt_e, *srt_x, *off_e, *off_n, *off_u, *deg, *cursor, *part;
    int2* srt_i;
    cudaGetSymbolAddress((void**)&nodeA,   g_nodeA);
    cudaGetSymbolAddress((void**)&nodeB,   g_nodeB);
    cudaGetSymbolAddress((void**)&entB,    g_entB);
    cudaGetSymbolAddress((void**)&entMean, g_entMean);
    cudaGetSymbolAddress((void**)&Q,       g_Q);
    cudaGetSymbolAddress((void**)&K,       g_K);
    cudaGetSymbolAddress((void**)&augp,    g_aug);
    cudaGetSymbolAddress((void**)&exps,    g_exps);
    cudaGetSymbolAddress((void**)&srt_e,   g_srt_ent);
    cudaGetSymbolAddress((void**)&srt_x,   g_srt_x);
    cudaGetSymbolAddress((void**)&srt_i,   g_srt_i);
    cudaGetSymbolAddress((void**)&off_e,   g_off_e);
    cudaGetSymbolAddress((void**)&off_n,   g_off_n);
    cudaGetSymbolAddress((void**)&off_u,   g_off_u);
    cudaGetSymbolAddress((void**)&deg,     g_deg);
    cudaGetSymbolAddress((void**)&cursor,  g_cursor);
    cudaGetSymbolAddress((void**)&part,    g_part);

    float* out = (float*)d_out;
    float* user_res = out;              // [n_users, C]
    float* ent_res  = out + UB;         // [n_ent, C]
    float* node_res = out + UB + EB;    // [n_nodes, C]

    // node embedding concat (needed by qk_gemm + hop1 node gather + node res init)
    cudaMemcpyAsync(nodeA,      user, UB * 4, cudaMemcpyDeviceToDevice);
    cudaMemcpyAsync(nodeA + UB, ent,  EB * 4, cudaMemcpyDeviceToDevice);

    const int* eh = eidx;          const int* et = eidx + E;
    const int* xh = exidx;         const int* xt = exidx + EX;

    // ---- CSR build: entity KG graph ----
    {
        int nb = (n_ent + 1023) >> 10;
        cudaMemsetAsync(deg, 0, (size_t)n_ent * 4);
        hist_k<<<(E + 255) / 256, 256>>>(eh, deg, E);
        scan_block<<<nb, 1024>>>(deg, off_e, part, n_ent);
        scan_part<<<1, 32>>>(part, nb);
        add_offs<<<(n_ent + 256) / 256 + 1, 256>>>(off_e, part, n_ent);
        cudaMemcpyAsync(cursor, off_e, (size_t)n_ent * 4, cudaMemcpyDeviceToDevice);
        scat_ent<<<(E + 255) / 256, 256>>>(eh, et, etype, cursor, srt_e, E);
    }
    // ---- CSR build: preference (extra) graph ----
    {
        int nb = (n_nodes + 1023) >> 10;
        cudaMemsetAsync(deg, 0, (size_t)n_nodes * 4);
        hist_k<<<(EX + 255) / 256, 256>>>(xh, deg, EX);
        scan_block<<<nb, 1024>>>(deg, off_n, part, n_nodes);
        scan_part<<<1, 32>>>(part, nb);
        add_offs<<<(n_nodes + 256) / 256 + 1, 256>>>(off_n, part, n_nodes);
        cudaMemcpyAsync(cursor, off_n, (size_t)n_nodes * 4, cudaMemcpyDeviceToDevice);
        scat_x<<<(EX + 255) / 256, 256>>>(xh, xt, cursor, srt_x, EX);
    }
    // ---- CSR build: interact matrix ----
    {
        int nb = (n_users + 1023) >> 10;
        cudaMemsetAsync(deg, 0, (size_t)n_users * 4);
        hist_k<<<(NNZ + 255) / 256, 256>>>(irows, deg, NNZ);
        scan_block<<<nb, 1024>>>(deg, off_u, part, n_users);
        scan_part<<<1, 32>>>(part, nb);
        add_offs<<<(n_users + 256) / 256 + 1, 256>>>(off_u, part, n_users);
        cudaMemcpyAsync(cursor, off_u, (size_t)n_users * 4, cudaMemcpyDeviceToDevice);
        scat_i<<<(NNZ + 255) / 256, 256>>>(irows, icols, ivals, cursor, srt_i, NNZ);
    }

    // ---- attention weights (once; reused both hops) ----
    cudaFuncSetAttribute(qk_gemm, cudaFuncAttributeMaxDynamicSharedMemorySize, 163840);
    qk_gemm<<<(n_nodes + 63) / 64, 512, 163840>>>(nodeA, WQ, WK, Q, K, n_nodes);
    attn_csr<<<(n_nodes * 32 + 255) / 256, 256>>>(off_n, srt_x, Q, K, exps, augp, n_nodes);

    // ---- hop 1 ----
    ent_agg_csr<<<(n_ent * 32 + 255) / 256, 256>>>(
        off_e, srt_e, ent, weight, entMean, entB, ent_res, ent, n_ent);
    user_agg_csr<<<(n_users * 32 + 255) / 256, 256>>>(
        off_u, srt_i, entMean, user_res, user, n_users);
    node_agg_csr<<<(n_nodes * 32 + 255) / 256, 256>>>(
        off_n, srt_x, augp, nodeA, nodeB, node_res, nodeA, n_nodes);

    // ---- hop 2 ----
    ent_agg_csr<<<(n_ent * 32 + 255) / 256, 256>>>(
        off_e, srt_e, entB, weight, entMean, (float*)0, ent_res, ent_res, n_ent);
    user_agg_csr<<<(n_users * 32 + 255) / 256, 256>>>(
        off_u, srt_i, entMean, user_res, user_res, n_users);
    node_agg_csr<<<(n_nodes * 32 + 255) / 256, 256>>>(
        off_n, srt_x, augp, nodeB, (float*)0, node_res, node_res, n_nodes);
}

// round 3
// speedup vs baseline: 1.9965x; 1.0811x over previous
#include <cuda_runtime.h>
#include <cuda_fp16.h>

#define C 128
#define MAX_USERS   50000
#define MAX_ENT     50000
#define MAX_NODES  100000
#define MAX_E     1000000

// ---------------- scratch (allocation-free: __device__ globals) ----------------
__device__ float  g_nodeA  [(size_t)MAX_NODES * C];   // fp32 concat [user; ent]
__device__ float  g_Q      [(size_t)MAX_NODES * C];
__device__ __half g_hNodeA [(size_t)MAX_NODES * C];   // half of nodeA (ent half = +UB)
__device__ __half g_hNodeB [(size_t)MAX_NODES * C];
__device__ __half g_hEntB  [(size_t)MAX_ENT   * C];
__device__ __half g_hEntM  [(size_t)MAX_ENT   * C];
__device__ __half g_hK     [(size_t)MAX_NODES * C];
__device__ int    g_srt_ent[MAX_E];
__device__ int    g_srt_x  [MAX_E];
__device__ int2   g_srt_i  [MAX_E];
__device__ float2 g_exps   [MAX_E];
__device__ float  g_aug    [MAX_E];
__device__ int g_off_e[MAX_ENT + 1];
__device__ int g_off_n[MAX_NODES + 1];
__device__ int g_off_u[MAX_USERS + 1];
__device__ int g_deg   [MAX_NODES];
__device__ int g_cursor[MAX_NODES];
__device__ int g_part  [256];

// ---------------- half pack/unpack ----------------
__device__ __forceinline__ uint2 pack4(float a, float b, float c, float d) {
    __half2 h0 = __floats2half2_rn(a, b);
    __half2 h1 = __floats2half2_rn(c, d);
    uint2 r; r.x = *(unsigned*)&h0; r.y = *(unsigned*)&h1; return r;
}
__device__ __forceinline__ float4 unpack4(uint2 v) {
    __half2 h0 = *(__half2*)&v.x, h1 = *(__half2*)&v.y;
    float2 f0 = __half22float2(h0), f1 = __half22float2(h1);
    return make_float4(f0.x, f0.y, f1.x, f1.y);
}

// ================= fp32 -> fp16 row conversion =================
__global__ __launch_bounds__(256) void conv_half(const float* __restrict__ src,
                                                 __half* __restrict__ dst, size_t n4)
{
    size_t i = (size_t)blockIdx.x * 256 + threadIdx.x;   // one float4 -> uint2
    if (i >= n4) return;
    float4 v = __ldg((const float4*)src + i);
    ((uint2*)dst)[i] = pack4(v.x, v.y, v.z, v.w);
}

// ================= CSR build =================
__global__ __launch_bounds__(256) void hist_k(const int* __restrict__ head, int* __restrict__ deg, int E)
{
    int i = blockIdx.x * 256 + threadIdx.x;
    if (i < E) atomicAdd(deg + __ldg(head + i), 1);
}

__global__ __launch_bounds__(1024) void scan_block(const int* __restrict__ deg,
                                                   int* __restrict__ off, int* __restrict__ part, int n)
{
    __shared__ int ws[32];
    int t = threadIdx.x;
    int gid = blockIdx.x * 1024 + t;
    int v = (gid < n) ? deg[gid] : 0;
    int x = v;
#pragma unroll
    for (int d = 1; d < 32; d <<= 1) {
        int y = __shfl_up_sync(0xffffffffu, x, d);
        if ((t & 31) >= d) x += y;
    }
    if ((t & 31) == 31) ws[t >> 5] = x;
    __syncthreads();
    if (t < 32) {
        int s = ws[t];
#pragma unroll
        for (int d = 1; d < 32; d <<= 1) {
            int y = __shfl_up_sync(0xffffffffu, s, d);
            if (t >= d) s += y;
        }
        ws[t] = s;
    }
    __syncthreads();
    int excl = x - v + ((t >= 32) ? ws[(t >> 5) - 1] : 0);
    if (gid < n) off[gid] = excl;
    if (t == 1023) part[blockIdx.x] = excl + v;
}

__global__ void scan_part(int* part, int nb)
{
    int t = threadIdx.x;   // 32 threads
    int v[4];
#pragma unroll
    for (int i = 0; i < 4; i++) { int idx = t * 4 + i; v[i] = (idx < nb) ? part[idx] : 0; }
    int loc = v[0] + v[1] + v[2] + v[3];
    int x = loc;
#pragma unroll
    for (int d = 1; d < 32; d <<= 1) {
        int y = __shfl_up_sync(0xffffffffu, x, d);
        if (t >= d) x += y;
    }
    int excl = x - loc;
#pragma unroll
    for (int i = 0; i < 4; i++) { int idx = t * 4 + i; if (idx < nb) part[idx] = excl; excl += v[i]; }
    if (t == 31) part[nb] = x;
}

__global__ __launch_bounds__(256) void add_offs(int* __restrict__ off, const int* __restrict__ part, int n)
{
    int i = blockIdx.x * 256 + threadIdx.x;
    if (i < n) off[i] += part[i >> 10];
    else if (i == n) off[i] = part[(n + 1023) >> 10];
}

__global__ __launch_bounds__(256) void scat_ent(const int* __restrict__ h, const int* __restrict__ t,
                                                const int* __restrict__ ty, int* __restrict__ cur,
                                                int* __restrict__ srt, int E)
{
    int e = blockIdx.x * 256 + threadIdx.x;
    if (e >= E) return;
    int p = atomicAdd(cur + __ldg(h + e), 1);
    srt[p] = __ldg(t + e) | ((__ldg(ty + e) - 1) << 16);
}

__global__ __launch_bounds__(256) void scat_x(const int* __restrict__ h, const int* __restrict__ t,
                                              int* __restrict__ cur, int* __restrict__ srt, int E)
{
    int e = blockIdx.x * 256 + threadIdx.x;
    if (e >= E) return;
    int p = atomicAdd(cur + __ldg(h + e), 1);
    srt[p] = __ldg(t + e);
}

__global__ __launch_bounds__(256) void scat_i(const int* __restrict__ r, const int* __restrict__ c,
                                              const float* __restrict__ v, int* __restrict__ cur,
                                              int2* __restrict__ srt, int E)
{
    int e = blockIdx.x * 256 + threadIdx.x;
    if (e >= E) return;
    int p = atomicAdd(cur + __ldg(r + e), 1);
    srt[p] = make_int2(__ldg(c + e), __float_as_int(__ldg(v + e)));
}

// ================= Q/K projection (Q fp32, K fp16) =================
__global__ __launch_bounds__(512) void qk_gemm(
    const float* __restrict__ node, const float* __restrict__ WQ,
    const float* __restrict__ WK, float* __restrict__ Q, __half* __restrict__ hK, int n)
{
    extern __shared__ float sm[];
    float* sW = sm;              // [2][128][128]
    float* sR = sm + 32768;      // [64][128]
    int t = threadIdx.x;
    int row0 = blockIdx.x * 64;

    for (int i = t; i < 8192; i += 512) {
        ((float4*)sW)[i] = (i < 4096) ? ((const float4*)WQ)[i]
                                      : ((const float4*)WK)[i - 4096];
    }
    for (int i = t; i < 2048; i += 512) {
        int r = i >> 5, c = i & 31;
        int gr = row0 + r;
        float4 v = make_float4(0.f, 0.f, 0.f, 0.f);
        if (gr < n) v = ((const float4*)(node + (size_t)gr * C))[c];
        ((float4*)sR)[i] = v;
    }
    __syncthreads();

    int lane = t & 31;
    int wid  = t >> 5;
    int mat  = wid & 1;
    int rg   = wid >> 1;
    const float* wbase = sW + mat * 16384 + lane * 4;
    const float* rbase = sR + rg * 8 * C;

    float acc[8][4];
#pragma unroll
    for (int r = 0; r < 8; r++)
#pragma unroll
        for (int c = 0; c < 4; c++) acc[r][c] = 0.f;

#pragma unroll 4
    for (int k = 0; k < 128; k += 4) {
        float4 w0 = *(const float4*)(wbase + (k + 0) * C);
        float4 w1 = *(const float4*)(wbase + (k + 1) * C);
        float4 w2 = *(const float4*)(wbase + (k + 2) * C);
        float4 w3 = *(const float4*)(wbase + (k + 3) * C);
#pragma unroll
        for (int r = 0; r < 8; r++) {
            float4 rv = *(const float4*)(rbase + r * C + k);
            acc[r][0] += rv.x * w0.x + rv.y * w1.x + rv.z * w2.x + rv.w * w3.x;
            acc[r][1] += rv.x * w0.y + rv.y * w1.y + rv.z * w2.y + rv.w * w3.y;
            acc[r][2] += rv.x * w0.z + rv.y * w1.z + rv.z * w2.z + rv.w * w3.z;
            acc[r][3] += rv.x * w0.w + rv.y * w1.w + rv.z * w2.w + rv.w * w3.w;
        }
    }

#pragma unroll
    for (int r = 0; r < 8; r++) {
        int gr = row0 + rg * 8 + r;
        if (gr < n) {
            if (mat == 0) {
                float4 o = make_float4(acc[r][0], acc[r][1], acc[r][2], acc[r][3]);
                ((float4*)(Q + (size_t)gr * C))[lane] = o;
            } else {
                ((uint2*)(hK + (size_t)gr * C))[lane] =
                    pack4(acc[r][0], acc[r][1], acc[r][2], acc[r][3]);
            }
        }
    }
}

// ================= fused attention (CSR): score, exp, row-z, aug =================
__global__ __launch_bounds__(256) void attn_csr(
    const int* __restrict__ off, const int* __restrict__ srt,
    const float* __restrict__ Q, const __half* __restrict__ K,
    float2* __restrict__ exps, float* __restrict__ aug, int n)
{
    int gw = (blockIdx.x * 256 + threadIdx.x) >> 5, lane = threadIdx.x & 31;
    if (gw >= n) return;
    int base = off[gw], end = off[gw + 1];
    if (base == end) return;
    float4 q = __ldg((const float4*)(Q + (size_t)gw * C) + lane);
    float z0 = 0.f, z1 = 0.f;
    for (int e0 = base; e0 < end; e0 += 32) {
        int cnt = min(32, end - e0);
        int meta = (lane < cnt) ? __ldg(srt + e0 + lane) : 0;
        float my0 = 0.f, my1 = 0.f;
        for (int j = 0; j < cnt; j++) {
            int tl = __shfl_sync(0xffffffffu, meta, j);
            float4 k4 = unpack4(__ldg((const uint2*)(K + (size_t)tl * C) + lane));
            float p = q.x * k4.x + q.y * k4.y + q.z * k4.z + q.w * k4.w;
            p += __shfl_xor_sync(0xffffffffu, p, 8);
            p += __shfl_xor_sync(0xffffffffu, p, 4);
            p += __shfl_xor_sync(0xffffffffu, p, 2);
            p += __shfl_xor_sync(0xffffffffu, p, 1);
            float po = __shfl_xor_sync(0xffffffffu, p, 16);
            float s0 = (lane < 16) ? p : po;
            float s1 = (lane < 16) ? po : p;
            float ex0 = __expf(s0 * 0.125f);
            float ex1 = __expf(s1 * 0.125f);
            z0 += ex0; z1 += ex1;
            if (lane == j) { my0 = ex0; my1 = ex1; }
        }
        if (lane < cnt) exps[e0 + lane] = make_float2(my0, my1);
    }
    float iz0 = 0.5f / z0, iz1 = 0.5f / z1;
    for (int e0 = base; e0 < end; e0 += 32) {
        int cnt = min(32, end - e0);
        if (lane < cnt) {
            float2 ex = exps[e0 + lane];
            aug[e0 + lane] = ex.x * iz0 + ex.y * iz1;
        }
    }
}

// ================= entity KG aggregation (CSR, fp16 gather, fused mean+norm+res) ========
__global__ __launch_bounds__(256) void ent_agg_csr(
    const int* __restrict__ off, const int* __restrict__ srt,
    const __half* __restrict__ src, const float* __restrict__ wgt,
    __half* __restrict__ mean_out, __half* __restrict__ cur_out,
    float* __restrict__ res, const float* __restrict__ res_init, int n)
{
    __shared__ float sW[15 * C];
    for (int i = threadIdx.x; i < 15 * C; i += 256) sW[i] = wgt[i];
    __syncthreads();
    int gw = (blockIdx.x * 256 + threadIdx.x) >> 5, lane = threadIdx.x & 31;
    if (gw >= n) return;
    int base = off[gw], end = off[gw + 1];
    float4 acc = make_float4(0.f, 0.f, 0.f, 0.f);
    for (int e0 = base; e0 < end; e0 += 32) {
        int cnt = min(32, end - e0);
        int meta = (lane < cnt) ? __ldg(srt + e0 + lane) : 0;
        int j = 0;
        for (; j + 4 <= cnt; j += 4) {
            int m0 = __shfl_sync(0xffffffffu, meta, j + 0);
            int m1 = __shfl_sync(0xffffffffu, meta, j + 1);
            int m2 = __shfl_sync(0xffffffffu, meta, j + 2);
            int m3 = __shfl_sync(0xffffffffu, meta, j + 3);
            float4 v0 = unpack4(__ldg((const uint2*)(src + (size_t)(m0 & 0xFFFF) * C) + lane));
            float4 v1 = unpack4(__ldg((const uint2*)(src + (size_t)(m1 & 0xFFFF) * C) + lane));
            float4 v2 = unpack4(__ldg((const uint2*)(src + (size_t)(m2 & 0xFFFF) * C) + lane));
            float4 v3 = unpack4(__ldg((const uint2*)(src + (size_t)(m3 & 0xFFFF) * C) + lane));
            float4 w0 = *((const float4*)(sW + (((unsigned)m0) >> 16) * C) + lane);
            float4 w1 = *((const float4*)(sW + (((unsigned)m1) >> 16) * C) + lane);
            float4 w2 = *((const float4*)(sW + (((unsigned)m2) >> 16) * C) + lane);
            float4 w3 = *((const float4*)(sW + (((unsigned)m3) >> 16) * C) + lane);
            acc.x += v0.x * w0.x + v1.x * w1.x + v2.x * w2.x + v3.x * w3.x;
            acc.y += v0.y * w0.y + v1.y * w1.y + v2.y * w2.y + v3.y * w3.y;
            acc.z += v0.z * w0.z + v1.z * w1.z + v2.z * w2.z + v3.z * w3.z;
            acc.w += v0.w * w0.w + v1.w * w1.w + v2.w * w2.w + v3.w * w3.w;
        }
        for (; j < cnt; j++) {
            int m0 = __shfl_sync(0xffffffffu, meta, j);
            float4 v0 = unpack4(__ldg((const uint2*)(src + (size_t)(m0 & 0xFFFF) * C) + lane));
            float4 w0 = *((const float4*)(sW + (((unsigned)m0) >> 16) * C) + lane);
            acc.x += v0.x * w0.x; acc.y += v0.y * w0.y;
            acc.z += v0.z * w0.z; acc.w += v0.w * w0.w;
        }
    }
    float inv = 1.0f / fmaxf((float)(end - base), 1.0f);
    float4 m = make_float4(acc.x * inv, acc.y * inv, acc.z * inv, acc.w * inv);
    ((uint2*)(mean_out + (size_t)gw * C))[lane] = pack4(m.x, m.y, m.z, m.w);
    float ss = m.x * m.x + m.y * m.y + m.z * m.z + m.w * m.w;
    ss += __shfl_xor_sync(0xffffffffu, ss, 16);
    ss += __shfl_xor_sync(0xffffffffu, ss, 8);
    ss += __shfl_xor_sync(0xffffffffu, ss, 4);
    ss += __shfl_xor_sync(0xffffffffu, ss, 2);
    ss += __shfl_xor_sync(0xffffffffu, ss, 1);
    float ni = 1.0f / fmaxf(sqrtf(ss), 1e-12f);
    float4 o = make_float4(m.x * ni, m.y * ni, m.z * ni, m.w * ni);
    if (cur_out) ((uint2*)(cur_out + (size_t)gw * C))[lane] = pack4(o.x, o.y, o.z, o.w);
    float4 r = __ldg((const float4*)(res_init + (size_t)gw * C) + lane);
    r.x += o.x; r.y += o.y; r.z += o.z; r.w += o.w;
    ((float4*)(res + (size_t)gw * C))[lane] = r;
}

// ================= preference-graph aggregation (CSR, fp16 gather, fused norm+res) ======
__global__ __launch_bounds__(256) void node_agg_csr(
    const int* __restrict__ off, const int* __restrict__ srt,
    const float* __restrict__ aug, const __half* __restrict__ src,
    __half* __restrict__ cur_out, float* __restrict__ res,
    const float* __restrict__ res_init, int n)
{
    int gw = (blockIdx.x * 256 + threadIdx.x) >> 5, lane = threadIdx.x & 31;
    if (gw >= n) return;
    int base = off[gw], end = off[gw + 1];
    float4 acc = make_float4(0.f, 0.f, 0.f, 0.f);
    for (int e0 = base; e0 < end; e0 += 32) {
        int cnt = min(32, end - e0);
        int meta = 0; float av = 0.f;
        if (lane < cnt) { meta = __ldg(srt + e0 + lane); av = __ldg(aug + e0 + lane); }
        int j = 0;
        for (; j + 4 <= cnt; j += 4) {
            int m0 = __shfl_sync(0xffffffffu, meta, j + 0);
            int m1 = __shfl_sync(0xffffffffu, meta, j + 1);
            int m2 = __shfl_sync(0xffffffffu, meta, j + 2);
            int m3 = __shfl_sync(0xffffffffu, meta, j + 3);
            float a0 = __shfl_sync(0xffffffffu, av, j + 0);
            float a1 = __shfl_sync(0xffffffffu, av, j + 1);
            float a2 = __shfl_sync(0xffffffffu, av, j + 2);
            float a3 = __shfl_sync(0xffffffffu, av, j + 3);
            float4 v0 = unpack4(__ldg((const uint2*)(src + (size_t)m0 * C) + lane));
            float4 v1 = unpack4(__ldg((const uint2*)(src + (size_t)m1 * C) + lane));
            float4 v2 = unpack4(__ldg((const uint2*)(src + (size_t)m2 * C) + lane));
            float4 v3 = unpack4(__ldg((const uint2*)(src + (size_t)m3 * C) + lane));
            acc.x += v0.x * a0 + v1.x * a1 + v2.x * a2 + v3.x * a3;
            acc.y += v0.y * a0 + v1.y * a1 + v2.y * a2 + v3.y * a3;
            acc.z += v0.z * a0 + v1.z * a1 + v2.z * a2 + v3.z * a3;
            acc.w += v0.w * a0 + v1.w * a1 + v2.w * a2 + v3.w * a3;
        }
        for (; j < cnt; j++) {
            int m0 = __shfl_sync(0xffffffffu, meta, j);
            float a0 = __shfl_sync(0xffffffffu, av, j);
            float4 v0 = unpack4(__ldg((const uint2*)(src + (size_t)m0 * C) + lane));
            acc.x += v0.x * a0; acc.y += v0.y * a0;
            acc.z += v0.z * a0; acc.w += v0.w * a0;
        }
    }
    // l2norm is scale-invariant: normalize the raw sum (mean division skipped)
    float ss = acc.x * acc.x + acc.y * acc.y + acc.z * acc.z + acc.w * acc.w;
    ss += __shfl_xor_sync(0xffffffffu, ss, 16);
    ss += __shfl_xor_sync(0xffffffffu, ss, 8);
    ss += __shfl_xor_sync(0xffffffffu, ss, 4);
    ss += __shfl_xor_sync(0xffffffffu, ss, 2);
    ss += __shfl_xor_sync(0xffffffffu, ss, 1);
    float ni = 1.0f / fmaxf(sqrtf(ss), 1e-12f);
    float4 o = make_float4(acc.x * ni, acc.y * ni, acc.z * ni, acc.w * ni);
    if (cur_out) ((uint2*)(cur_out + (size_t)gw * C))[lane] = pack4(o.x, o.y, o.z, o.w);
    float4 r = __ldg((const float4*)(res_init + (size_t)gw * C) + lane);
    r.x += o.x; r.y += o.y; r.z += o.z; r.w += o.w;
    ((float4*)(res + (size_t)gw * C))[lane] = r;
}

// ================= interact-mat aggregation (CSR, fp16 gather, fused norm+res) ==========
__global__ __launch_bounds__(256) void user_agg_csr(
    const int* __restrict__ off, const int2* __restrict__ srt,
    const __half* __restrict__ src, float* __restrict__ res,
    const float* __restrict__ res_init, int n)
{
    int gw = (blockIdx.x * 256 + threadIdx.x) >> 5, lane = threadIdx.x & 31;
    if (gw >= n) return;
    int base = off[gw], end = off[gw + 1];
    float4 acc = make_float4(0.f, 0.f, 0.f, 0.f);
    for (int e0 = base; e0 < end; e0 += 32) {
        int cnt = min(32, end - e0);
        int mc = 0; float mv = 0.f;
        if (lane < cnt) { int2 p = __ldg(srt + e0 + lane); mc = p.x; mv = __int_as_float(p.y); }
        int j = 0;
        for (; j + 4 <= cnt; j += 4) {
            int c0 = __shfl_sync(0xffffffffu, mc, j + 0);
            int c1 = __shfl_sync(0xffffffffu, mc, j + 1);
            int c2 = __shfl_sync(0xffffffffu, mc, j + 2);
            int c3 = __shfl_sync(0xffffffffu, mc, j + 3);
            float a0 = __shfl_sync(0xffffffffu, mv, j + 0);
            float a1 = __shfl_sync(0xffffffffu, mv, j + 1);
            float a2 = __shfl_sync(0xffffffffu, mv, j + 2);
            float a3 = __shfl_sync(0xffffffffu, mv, j + 3);
            float4 v0 = unpack4(__ldg((const uint2*)(src + (size_t)c0 * C) + lane));
            float4 v1 = unpack4(__ldg((const uint2*)(src + (size_t)c1 * C) + lane));
            float4 v2 = unpack4(__ldg((const uint2*)(src + (size_t)c2 * C) + lane));
            float4 v3 = unpack4(__ldg((const uint2*)(src + (size_t)c3 * C) + lane));
            acc.x += v0.x * a0 + v1.x * a1 + v2.x * a2 + v3.x * a3;
            acc.y += v0.y * a0 + v1.y * a1 + v2.y * a2 + v3.y * a3;
            acc.z += v0.z * a0 + v1.z * a1 + v2.z * a2 + v3.z * a3;
            acc.w += v0.w * a0 + v1.w * a1 + v2.w * a2 + v3.w * a3;
        }
        for (; j < cnt; j++) {
            int c0 = __shfl_sync(0xffffffffu, mc, j);
            float a0 = __shfl_sync(0xffffffffu, mv, j);
            float4 v0 = unpack4(__ldg((const uint2*)(src + (size_t)c0 * C) + lane));
            acc.x += v0.x * a0; acc.y += v0.y * a0;
            acc.z += v0.z * a0; acc.w += v0.w * a0;
        }
    }
    float ss = acc.x * acc.x + acc.y * acc.y + acc.z * acc.z + acc.w * acc.w;
    ss += __shfl_xor_sync(0xffffffffu, ss, 16);
    ss += __shfl_xor_sync(0xffffffffu, ss, 8);
    ss += __shfl_xor_sync(0xffffffffu, ss, 4);
    ss += __shfl_xor_sync(0xffffffffu, ss, 2);
    ss += __shfl_xor_sync(0xffffffffu, ss, 1);
    float ni = 1.0f / fmaxf(sqrtf(ss), 1e-12f);
    float4 o = make_float4(acc.x * ni, acc.y * ni, acc.z * ni, acc.w * ni);
    float4 r = __ldg((const float4*)(res_init + (size_t)gw * C) + lane);
    r.x += o.x; r.y += o.y; r.z += o.z; r.w += o.w;
    ((float4*)(res + (size_t)gw * C))[lane] = r;
}

// ================= host launcher =================
extern "C" void kernel_launch(void* const* d_in, const int* in_sizes, int n_in,
                              void* d_out, int out_size)
{
    const float* user   = (const float*)d_in[0];
    const float* ent    = (const float*)d_in[1];
    const int*   eidx   = (const int*)  d_in[2];
    const int*   etype  = (const int*)  d_in[3];
    const int*   exidx  = (const int*)  d_in[4];
    const int*   irows  = (const int*)  d_in[6];
    const int*   icols  = (const int*)  d_in[7];
    const float* ivals  = (const float*)d_in[8];
    const float* weight = (const float*)d_in[9];
    const float* WQ     = (const float*)d_in[11];
    const float* WK     = (const float*)d_in[12];

    int n_users = in_sizes[0] / C;
    int n_ent   = in_sizes[1] / C;
    int n_nodes = n_users + n_ent;
    int E   = in_sizes[3];
    int EX  = in_sizes[5];
    int NNZ = in_sizes[6];

    size_t UB = (size_t)n_users * C;
    size_t EB = (size_t)n_ent * C;

    float *nodeA, *Q, *augp;
    __half *hNodeA, *hNodeB, *hEntB, *hEntM, *hK;
    float2* exps;
    int *srt_e, *srt_x, *off_e, *off_n, *off_u, *deg, *cursor, *part;
    int2* srt_i;
    cudaGetSymbolAddress((void**)&nodeA,  g_nodeA);
    cudaGetSymbolAddress((void**)&Q,      g_Q);
    cudaGetSymbolAddress((void**)&hNodeA, g_hNodeA);
    cudaGetSymbolAddress((void**)&hNodeB, g_hNodeB);
    cudaGetSymbolAddress((void**)&hEntB,  g_hEntB);
    cudaGetSymbolAddress((void**)&hEntM,  g_hEntM);
    cudaGetSymbolAddress((void**)&hK,     g_hK);
    cudaGetSymbolAddress((void**)&augp,   g_aug);
    cudaGetSymbolAddress((void**)&exps,   g_exps);
    cudaGetSymbolAddress((void**)&srt_e,  g_srt_ent);
    cudaGetSymbolAddress((void**)&srt_x,  g_srt_x);
    cudaGetSymbolAddress((void**)&srt_i,  g_srt_i);
    cudaGetSymbolAddress((void**)&off_e,  g_off_e);
    cudaGetSymbolAddress((void**)&off_n,  g_off_n);
    cudaGetSymbolAddress((void**)&off_u,  g_off_u);
    cudaGetSymbolAddress((void**)&deg,    g_deg);
    cudaGetSymbolAddress((void**)&cursor, g_cursor);
    cudaGetSymbolAddress((void**)&part,   g_part);

    float* out = (float*)d_out;
    float* user_res = out;              // [n_users, C]
    float* ent_res  = out + UB;         // [n_ent, C]
    float* node_res = out + UB + EB;    // [n_nodes, C]

    // node embedding concat (fp32, for qk_gemm + hop1 node res_init)
    cudaMemcpyAsync(nodeA,      user, UB * 4, cudaMemcpyDeviceToDevice);
    cudaMemcpyAsync(nodeA + UB, ent,  EB * 4, cudaMemcpyDeviceToDevice);
    // fp16 copy of node embeddings; entity half is hNodeA + UB
    {
        size_t n4 = (size_t)n_nodes * 32;
        conv_half<<<(unsigned)((n4 + 255) / 256), 256>>>(nodeA, hNodeA, n4);
    }

    const int* eh = eidx;          const int* et = eidx + E;
    const int* xh = exidx;         const int* xt = exidx + EX;

    // ---- CSR build: entity KG graph ----
    {
        int nb = (n_ent + 1023) >> 10;
        cudaMemsetAsync(deg, 0, (size_t)n_ent * 4);
        hist_k<<<(E + 255) / 256, 256>>>(eh, deg, E);
        scan_block<<<nb, 1024>>>(deg, off_e, part, n_ent);
        scan_part<<<1, 32>>>(part, nb);
        add_offs<<<(n_ent + 256) / 256 + 1, 256>>>(off_e, part, n_ent);
        cudaMemcpyAsync(cursor, off_e, (size_t)n_ent * 4, cudaMemcpyDeviceToDevice);
        scat_ent<<<(E + 255) / 256, 256>>>(eh, et, etype, cursor, srt_e, E);
    }
    // ---- CSR build: preference (extra) graph ----
    {
        int nb = (n_nodes + 1023) >> 10;
        cudaMemsetAsync(deg, 0, (size_t)n_nodes * 4);
        hist_k<<<(EX + 255) / 256, 256>>>(xh, deg, EX);
        scan_block<<<nb, 1024>>>(deg, off_n, part, n_nodes);
        scan_part<<<1, 32>>>(part, nb);
        add_offs<<<(n_nodes + 256) / 256 + 1, 256>>>(off_n, part, n_nodes);
        cudaMemcpyAsync(cursor, off_n, (size_t)n_nodes * 4, cudaMemcpyDeviceToDevice);
        scat_x<<<(EX + 255) / 256, 256>>>(xh, xt, cursor, srt_x, EX);
    }
    // ---- CSR build: interact matrix ----
    {
        int nb = (n_users + 1023) >> 10;
        cudaMemsetAsync(deg, 0, (size_t)n_users * 4);
        hist_k<<<(NNZ + 255) / 256, 256>>>(irows, deg, NNZ);
        scan_block<<<nb, 1024>>>(deg, off_u, part, n_users);
        scan_part<<<1, 32>>>(part, nb);
        add_offs<<<(n_users + 256) / 256 + 1, 256>>>(off_u, part, n_users);
        cudaMemcpyAsync(cursor, off_u, (size_t)n_users * 4, cudaMemcpyDeviceToDevice);
        scat_i<<<(NNZ + 255) / 256, 256>>>(irows, icols, ivals, cursor, srt_i, NNZ);
    }

    // ---- attention weights (once; reused both hops) ----
    cudaFuncSetAttribute(qk_gemm, cudaFuncAttributeMaxDynamicSharedMemorySize, 163840);
    qk_gemm<<<(n_nodes + 63) / 64, 512, 163840>>>(nodeA, WQ, WK, Q, hK, n_nodes);
    attn_csr<<<(n_nodes * 32 + 255) / 256, 256>>>(off_n, srt_x, Q, hK, exps, augp, n_nodes);

    // ---- hop 1 ----
    ent_agg_csr<<<(n_ent * 32 + 255) / 256, 256>>>(
        off_e, srt_e, hNodeA + UB, weight, hEntM, hEntB, ent_res, ent, n_ent);
    user_agg_csr<<<(n_users * 32 + 255) / 256, 256>>>(
        off_u, srt_i, hEntM, user_res, user, n_users);
    node_agg_csr<<<(n_nodes * 32 + 255) / 256, 256>>>(
        off_n, srt_x, augp, hNodeA, hNodeB, node_res, nodeA, n_nodes);

    // ---- hop 2 ----
    ent_agg_csr<<<(n_ent * 32 + 255) / 256, 256>>>(
        off_e, srt_e, hEntB, weight, hEntM, (__half*)0, ent_res, ent_res, n_ent);
    user_agg_csr<<<(n_users * 32 + 255) / 256, 256>>>(
        off_u, srt_i, hEntM, user_res, user_res, n_users);
    node_agg_csr<<<(n_nodes * 32 + 255) / 256, 256>>>(
        off_n, srt_x, augp, hNodeB, (__half*)0, node_res, node_res, n_nodes);
}

// round 4
// speedup vs baseline: 2.7196x; 1.3622x over previous
#include <cuda_runtime.h>
#include <cuda_fp16.h>

#define C 128
#define MAX_USERS   50000
#define MAX_ENT     50000
#define MAX_NODES  100000
#define MAX_E     1000000
#define DEGS 100000          // deg segment stride
#define OFFS 100008          // off/cursor segment stride
#define PS   132             // partials segment stride

// ---------------- scratch (allocation-free: __device__ globals) ----------------
__device__ __half g_hNodeA [(size_t)MAX_NODES * C];
__device__ __half g_hNodeB [(size_t)MAX_NODES * C];
__device__ __half g_hEntB  [(size_t)MAX_ENT   * C];
__device__ __half g_hEntM  [(size_t)MAX_ENT   * C];
__device__ __half g_hQ     [(size_t)MAX_NODES * C];
__device__ __half g_hK     [(size_t)MAX_NODES * C];
__device__ __half g_WT     [2 * C * C];               // [mat][n][k] fp16 (W transposed)
__device__ int    g_srt_ent[MAX_E];
__device__ int    g_srt_x  [MAX_E];
__device__ int2   g_srt_i  [MAX_E];
__device__ float2 g_exps   [MAX_E];
__device__ float  g_aug    [MAX_E];
__device__ int    g_deg3   [3 * DEGS];
__device__ int    g_off3   [3 * OFFS];
__device__ int    g_cur3   [3 * OFFS];
__device__ int    g_part3  [3 * PS];

// ---------------- half pack/unpack ----------------
__device__ __forceinline__ uint2 pack4(float a, float b, float c, float d) {
    __half2 h0 = __floats2half2_rn(a, b);
    __half2 h1 = __floats2half2_rn(c, d);
    uint2 r; r.x = *(unsigned*)&h0; r.y = *(unsigned*)&h1; return r;
}
__device__ __forceinline__ float4 unpack4(uint2 v) {
    __half2 h0 = *(__half2*)&v.x, h1 = *(__half2*)&v.y;
    float2 f0 = __half22float2(h0), f1 = __half22float2(h1);
    return make_float4(f0.x, f0.y, f1.x, f1.y);
}

// ================= fp32 (user|ent) -> fp16 concat =================
__global__ __launch_bounds__(256) void conv2(const float* __restrict__ a,
                                             const float* __restrict__ b,
                                             size_t n4a, size_t n4, __half* __restrict__ dst)
{
    size_t i = (size_t)blockIdx.x * 256 + threadIdx.x;   // one float4 -> uint2
    if (i >= n4) return;
    float4 v = (i < n4a) ? __ldg((const float4*)a + i) : __ldg((const float4*)b + (i - n4a));
    ((uint2*)dst)[i] = pack4(v.x, v.y, v.z, v.w);
}

// ================= W fp32 [k][n] -> fp16 transposed [mat][n][k] =================
__global__ __launch_bounds__(256) void wt_conv(const float* __restrict__ WQ,
                                               const float* __restrict__ WK,
                                               __half* __restrict__ WT)
{
    int i = blockIdx.x * 256 + threadIdx.x;   // i over 2*128*128
    if (i >= 2 * C * C) return;
    int mat = i >> 14, r = i & 16383;
    int k = r >> 7, n = r & 127;              // read coalesced over n
    float v = mat ? __ldg(WK + r) : __ldg(WQ + r);
    WT[mat * C * C + n * C + k] = __float2half_rn(v);
}

// ================= CSR build (batched over the 3 graphs) =================
__global__ __launch_bounds__(256) void hist3(
    const int* __restrict__ h_e, int E1,
    const int* __restrict__ h_x, int E2,
    const int* __restrict__ h_u, int E3, int* __restrict__ deg3)
{
    int i = blockIdx.x * 256 + threadIdx.x;
    if (i < E1) { atomicAdd(deg3 + __ldg(h_e + i), 1); return; }
    i -= E1;
    if (i < E2) { atomicAdd(deg3 + DEGS + __ldg(h_x + i), 1); return; }
    i -= E2;
    if (i < E3) atomicAdd(deg3 + 2 * DEGS + __ldg(h_u + i), 1);
}

__global__ __launch_bounds__(1024) void scan_block3(const int* __restrict__ deg3,
                                                    int* __restrict__ off3, int* __restrict__ part3,
                                                    int n0, int n1, int n2)
{
    __shared__ int ws[32];
    int y = blockIdx.y;
    int n = (y == 0) ? n0 : ((y == 1) ? n1 : n2);
    const int* deg = deg3 + y * DEGS;
    int* off = off3 + y * OFFS;
    int* part = part3 + y * PS;
    int t = threadIdx.x;
    int gid = blockIdx.x * 1024 + t;
    int v = (gid < n) ? deg[gid] : 0;
    int x = v;
#pragma unroll
    for (int d = 1; d < 32; d <<= 1) {
        int yv = __shfl_up_sync(0xffffffffu, x, d);
        if ((t & 31) >= d) x += yv;
    }
    if ((t & 31) == 31) ws[t >> 5] = x;
    __syncthreads();
    if (t < 32) {
        int s = ws[t];
#pragma unroll
        for (int d = 1; d < 32; d <<= 1) {
            int yv = __shfl_up_sync(0xffffffffu, s, d);
            if (t >= d) s += yv;
        }
        ws[t] = s;
    }
    __syncthreads();
    int excl = x - v + ((t >= 32) ? ws[(t >> 5) - 1] : 0);
    if (gid < n) off[gid] = excl;
    if (t == 1023) part[blockIdx.x] = excl + v;
}

// 3 warps, one per graph; each scans 128 partials (exclusive)
__global__ void scan_part3(int* __restrict__ part3)
{
    int t = threadIdx.x;            // 96 threads
    int w = t >> 5, lane = t & 31;
    int* part = part3 + w * PS;
    int v[4];
#pragma unroll
    for (int i = 0; i < 4; i++) v[i] = part[lane * 4 + i];
    int loc = v[0] + v[1] + v[2] + v[3];
    int x = loc;
#pragma unroll
    for (int d = 1; d < 32; d <<= 1) {
        int y = __shfl_up_sync(0xffffffffu, x, d);
        if (lane >= d) x += y;
    }
    int excl = x - loc;
#pragma unroll
    for (int i = 0; i < 4; i++) { part[lane * 4 + i] = excl; excl += v[i]; }
}

__global__ __launch_bounds__(256) void add_offs3(int* __restrict__ off3,
                                                 const int* __restrict__ part3,
                                                 int n0, int n1, int n2)
{
    int y = blockIdx.y;
    int n = (y == 0) ? n0 : ((y == 1) ? n1 : n2);
    int* off = off3 + y * OFFS;
    const int* part = part3 + y * PS;
    int i = blockIdx.x * 256 + threadIdx.x;
    if (i < n) off[i] += part[i >> 10];
    else if (i == n) off[i] = part[(n + 1023) >> 10];
}

__global__ __launch_bounds__(256) void scat3(
    const int* __restrict__ eh, const int* __restrict__ et, const int* __restrict__ ety, int E1,
    const int* __restrict__ xh, const int* __restrict__ xt, int E2,
    const int* __restrict__ ir, const int* __restrict__ ic, const float* __restrict__ iv, int E3,
    int* __restrict__ cur3, int* __restrict__ srt_e, int* __restrict__ srt_x, int2* __restrict__ srt_i)
{
    int i = blockIdx.x * 256 + threadIdx.x;
    if (i < E1) {
        int p = atomicAdd(cur3 + __ldg(eh + i), 1);
        srt_e[p] = __ldg(et + i) | ((__ldg(ety + i) - 1) << 16);
        return;
    }
    i -= E1;
    if (i < E2) {
        int p = atomicAdd(cur3 + OFFS + __ldg(xh + i), 1);
        srt_x[p] = __ldg(xt + i);
        return;
    }
    i -= E2;
    if (i < E3) {
        int p = atomicAdd(cur3 + 2 * OFFS + __ldg(ir + i), 1);
        srt_i[p] = make_int2(__ldg(ic + i), __float_as_int(__ldg(iv + i)));
    }
}

// ================= Q/K projection via HMMA (m16n8k16, fp16 in, fp32 acc) =================
// Block: 256 threads (8 warps), 64 rows per block, N=256 (Q cols 0-127 | K cols 128-255).
// Warp tile: 16 rows x 64 cols; warps: rg = wid&3 (4 x 16 rows), cg = wid>>2 (2 x 64 cols).
// smem: sB [2][128n][136k] fp16 (padded, conflict-free), sA [64][136] fp16.
#define SB_H (2 * 128 * 136)
#define SA_H (64 * 136)
__global__ __launch_bounds__(256) void qk_mma(
    const __half* __restrict__ node, const __half* __restrict__ WT,
    __half* __restrict__ Q, __half* __restrict__ K, int n)
{
    extern __shared__ __half sh[];
    __half* sB = sh;            // [mat*128 + n][136]
    __half* sA = sh + SB_H;     // [row][136]
    int t = threadIdx.x;
    int row0 = blockIdx.x * 64;

    // load W^T: 2*128*128 fp16 = 4096 uint4; each uint4 = 8 consecutive k of one n
    for (int i = t; i < 4096; i += 256) {
        uint4 v = __ldg((const uint4*)WT + i);
        int nn = i >> 4, k8 = (i & 15) << 3;
        *(uint4*)(sB + nn * 136 + k8) = v;
    }
    // load A tile: 64 rows x 128 fp16 = 1024 uint4
    for (int i = t; i < 1024; i += 256) {
        int r = i >> 4, k8 = (i & 15) << 3;
        int gr = row0 + r;
        uint4 v = make_uint4(0u, 0u, 0u, 0u);
        if (gr < n) v = __ldg((const uint4*)(node + (size_t)gr * C) + (i & 15));
        *(uint4*)(sA + r * 136 + k8) = v;
    }
    __syncthreads();

    int lane = t & 31, wid = t >> 5;
    int rg = wid & 3, cg = wid >> 2;
    int arow = rg * 16 + (lane >> 2);
    int kq = (lane & 3) * 2;

#pragma unroll
    for (int mat = 0; mat < 2; mat++) {
        float acc[8][4];
#pragma unroll
        for (int nt = 0; nt < 8; nt++)
#pragma unroll
            for (int c = 0; c < 4; c++) acc[nt][c] = 0.f;

#pragma unroll
        for (int kk = 0; kk < 128; kk += 16) {
            unsigned a0 = *(unsigned*)(sA + arow * 136 + kk + kq);
            unsigned a1 = *(unsigned*)(sA + (arow + 8) * 136 + kk + kq);
            unsigned a2 = *(unsigned*)(sA + arow * 136 + kk + kq + 8);
            unsigned a3 = *(unsigned*)(sA + (arow + 8) * 136 + kk + kq + 8);
#pragma unroll
            for (int nt = 0; nt < 8; nt++) {
                int nn = mat * 128 + cg * 64 + nt * 8 + (lane >> 2);
                unsigned b0 = *(unsigned*)(sB + nn * 136 + kk + kq);
                unsigned b1 = *(unsigned*)(sB + nn * 136 + kk + kq + 8);
                asm volatile(
                    "mma.sync.aligned.m16n8k16.row.col.f32.f16.f16.f32 "
                    "{%0,%1,%2,%3}, {%4,%5,%6,%7}, {%8,%9}, {%0,%1,%2,%3};"
                    : "+f"(acc[nt][0]), "+f"(acc[nt][1]), "+f"(acc[nt][2]), "+f"(acc[nt][3])
                    : "r"(a0), "r"(a1), "r"(a2), "r"(a3), "r"(b0), "r"(b1));
            }
        }

        __half* outb = mat ? K : Q;
        int grow = row0 + rg * 16 + (lane >> 2);
#pragma unroll
        for (int nt = 0; nt < 8; nt++) {
            int col = cg * 64 + nt * 8 + (lane & 3) * 2;
            if (grow < n) {
                __half2 h = __floats2half2_rn(acc[nt][0], acc[nt][1]);
                *(__half2*)(outb + (size_t)grow * C + col) = h;
            }
            if (grow + 8 < n) {
                __half2 h = __floats2half2_rn(acc[nt][2], acc[nt][3]);
                *(__half2*)(outb + (size_t)(grow + 8) * C + col) = h;
            }
        }
    }
}

// ================= fused attention (CSR): score, exp, row-z, aug =================
__global__ __launch_bounds__(256) void attn_csr(
    const int* __restrict__ off, const int* __restrict__ srt,
    const __half* __restrict__ Q, const __half* __restrict__ K,
    float2* __restrict__ exps, float* __restrict__ aug, int n)
{
    int gw = (blockIdx.x * 256 + threadIdx.x) >> 5, lane = threadIdx.x & 31;
    if (gw >= n) return;
    int base = off[gw], end = off[gw + 1];
    if (base == end) return;
    float4 q = unpack4(__ldg((const uint2*)(Q + (size_t)gw * C) + lane));
    float z0 = 0.f, z1 = 0.f;
    for (int e0 = base; e0 < end; e0 += 32) {
        int cnt = min(32, end - e0);
        int meta = (lane < cnt) ? __ldg(srt + e0 + lane) : 0;
        float my0 = 0.f, my1 = 0.f;
        for (int j = 0; j < cnt; j++) {
            int tl = __shfl_sync(0xffffffffu, meta, j);
            float4 k4 = unpack4(__ldg((const uint2*)(K + (size_t)tl * C) + lane));
            float p = q.x * k4.x + q.y * k4.y + q.z * k4.z + q.w * k4.w;
            p += __shfl_xor_sync(0xffffffffu, p, 8);
            p += __shfl_xor_sync(0xffffffffu, p, 4);
            p += __shfl_xor_sync(0xffffffffu, p, 2);
            p += __shfl_xor_sync(0xffffffffu, p, 1);
            float po = __shfl_xor_sync(0xffffffffu, p, 16);
            float s0 = (lane < 16) ? p : po;
            float s1 = (lane < 16) ? po : p;
            float ex0 = __expf(s0 * 0.125f);
            float ex1 = __expf(s1 * 0.125f);
            z0 += ex0; z1 += ex1;
            if (lane == j) { my0 = ex0; my1 = ex1; }
        }
        if (lane < cnt) exps[e0 + lane] = make_float2(my0, my1);
    }
    float iz0 = 0.5f / z0, iz1 = 0.5f / z1;
    for (int e0 = base; e0 < end; e0 += 32) {
        int cnt = min(32, end - e0);
        if (lane < cnt) {
            float2 ex = exps[e0 + lane];
            aug[e0 + lane] = ex.x * iz0 + ex.y * iz1;
        }
    }
}

// ================= entity KG aggregation (CSR, fp16 gather, fused mean+norm+res) ========
__global__ __launch_bounds__(256) void ent_agg_csr(
    const int* __restrict__ off, const int* __restrict__ srt,
    const __half* __restrict__ src, const float* __restrict__ wgt,
    __half* __restrict__ mean_out, __half* __restrict__ cur_out,
    float* __restrict__ res, const float* __restrict__ res_init, int n)
{
    __shared__ float sW[15 * C];
    for (int i = threadIdx.x; i < 15 * C; i += 256) sW[i] = wgt[i];
    __syncthreads();
    int gw = (blockIdx.x * 256 + threadIdx.x) >> 5, lane = threadIdx.x & 31;
    if (gw >= n) return;
    int base = off[gw], end = off[gw + 1];
    float4 acc = make_float4(0.f, 0.f, 0.f, 0.f);
    for (int e0 = base; e0 < end; e0 += 32) {
        int cnt = min(32, end - e0);
        int meta = (lane < cnt) ? __ldg(srt + e0 + lane) : 0;
        int j = 0;
        for (; j + 4 <= cnt; j += 4) {
            int m0 = __shfl_sync(0xffffffffu, meta, j + 0);
            int m1 = __shfl_sync(0xffffffffu, meta, j + 1);
            int m2 = __shfl_sync(0xffffffffu, meta, j + 2);
            int m3 = __shfl_sync(0xffffffffu, meta, j + 3);
            float4 v0 = unpack4(__ldg((const uint2*)(src + (size_t)(m0 & 0xFFFF) * C) + lane));
            float4 v1 = unpack4(__ldg((const uint2*)(src + (size_t)(m1 & 0xFFFF) * C) + lane));
            float4 v2 = unpack4(__ldg((const uint2*)(src + (size_t)(m2 & 0xFFFF) * C) + lane));
            float4 v3 = unpack4(__ldg((const uint2*)(src + (size_t)(m3 & 0xFFFF) * C) + lane));
            float4 w0 = *((const float4*)(sW + (((unsigned)m0) >> 16) * C) + lane);
            float4 w1 = *((const float4*)(sW + (((unsigned)m1) >> 16) * C) + lane);
            float4 w2 = *((const float4*)(sW + (((unsigned)m2) >> 16) * C) + lane);
            float4 w3 = *((const float4*)(sW + (((unsigned)m3) >> 16) * C) + lane);
            acc.x += v0.x * w0.x + v1.x * w1.x + v2.x * w2.x + v3.x * w3.x;
            acc.y += v0.y * w0.y + v1.y * w1.y + v2.y * w2.y + v3.y * w3.y;
            acc.z += v0.z * w0.z + v1.z * w1.z + v2.z * w2.z + v3.z * w3.z;
            acc.w += v0.w * w0.w + v1.w * w1.w + v2.w * w2.w + v3.w * w3.w;
        }
        for (; j < cnt; j++) {
            int m0 = __shfl_sync(0xffffffffu, meta, j);
            float4 v0 = unpack4(__ldg((const uint2*)(src + (size_t)(m0 & 0xFFFF) * C) + lane));
            float4 w0 = *((const float4*)(sW + (((unsigned)m0) >> 16) * C) + lane);
            acc.x += v0.x * w0.x; acc.y += v0.y * w0.y;
            acc.z += v0.z * w0.z; acc.w += v0.w * w0.w;
        }
    }
    float inv = 1.0f / fmaxf((float)(end - base), 1.0f);
    float4 m = make_float4(acc.x * inv, acc.y * inv, acc.z * inv, acc.w * inv);
    ((uint2*)(mean_out + (size_t)gw * C))[lane] = pack4(m.x, m.y, m.z, m.w);
    float ss = m.x * m.x + m.y * m.y + m.z * m.z + m.w * m.w;
    ss += __shfl_xor_sync(0xffffffffu, ss, 16);
    ss += __shfl_xor_sync(0xffffffffu, ss, 8);
    ss += __shfl_xor_sync(0xffffffffu, ss, 4);
    ss += __shfl_xor_sync(0xffffffffu, ss, 2);
    ss += __shfl_xor_sync(0xffffffffu, ss, 1);
    float ni = 1.0f / fmaxf(sqrtf(ss), 1e-12f);
    float4 o = make_float4(m.x * ni, m.y * ni, m.z * ni, m.w * ni);
    if (cur_out) ((uint2*)(cur_out + (size_t)gw * C))[lane] = pack4(o.x, o.y, o.z, o.w);
    float4 r = __ldg((const float4*)(res_init + (size_t)gw * C) + lane);
    r.x += o.x; r.y += o.y; r.z += o.z; r.w += o.w;
    ((float4*)(res + (size_t)gw * C))[lane] = r;
}

// ================= preference-graph aggregation (CSR, fp16 gather, fused norm+res) ======
__global__ __launch_bounds__(256) void node_agg_csr(
    const int* __restrict__ off, const int* __restrict__ srt,
    const float* __restrict__ aug, const __half* __restrict__ src,
    __half* __restrict__ cur_out, float* __restrict__ res,
    const float* __restrict__ ri0, const float* __restrict__ ri1, int split, int n)
{
    int gw = (blockIdx.x * 256 + threadIdx.x) >> 5, lane = threadIdx.x & 31;
    if (gw >= n) return;
    int base = off[gw], end = off[gw + 1];
    float4 acc = make_float4(0.f, 0.f, 0.f, 0.f);
    for (int e0 = base; e0 < end; e0 += 32) {
        int cnt = min(32, end - e0);
        int meta = 0; float av = 0.f;
        if (lane < cnt) { meta = __ldg(srt + e0 + lane); av = __ldg(aug + e0 + lane); }
        int j = 0;
        for (; j + 4 <= cnt; j += 4) {
            int m0 = __shfl_sync(0xffffffffu, meta, j + 0);
            int m1 = __shfl_sync(0xffffffffu, meta, j + 1);
            int m2 = __shfl_sync(0xffffffffu, meta, j + 2);
            int m3 = __shfl_sync(0xffffffffu, meta, j + 3);
            float a0 = __shfl_sync(0xffffffffu, av, j + 0);
            float a1 = __shfl_sync(0xffffffffu, av, j + 1);
            float a2 = __shfl_sync(0xffffffffu, av, j + 2);
            float a3 = __shfl_sync(0xffffffffu, av, j + 3);
            float4 v0 = unpack4(__ldg((const uint2*)(src + (size_t)m0 * C) + lane));
            float4 v1 = unpack4(__ldg((const uint2*)(src + (size_t)m1 * C) + lane));
            float4 v2 = unpack4(__ldg((const uint2*)(src + (size_t)m2 * C) + lane));
            float4 v3 = unpack4(__ldg((const uint2*)(src + (size_t)m3 * C) + lane));
            acc.x += v0.x * a0 + v1.x * a1 + v2.x * a2 + v3.x * a3;
            acc.y += v0.y * a0 + v1.y * a1 + v2.y * a2 + v3.y * a3;
            acc.z += v0.z * a0 + v1.z * a1 + v2.z * a2 + v3.z * a3;
            acc.w += v0.w * a0 + v1.w * a1 + v2.w * a2 + v3.w * a3;
        }
        for (; j < cnt; j++) {
            int m0 = __shfl_sync(0xffffffffu, meta, j);
            float a0 = __shfl_sync(0xffffffffu, av, j);
            float4 v0 = unpack4(__ldg((const uint2*)(src + (size_t)m0 * C) + lane));
            acc.x += v0.x * a0; acc.y += v0.y * a0;
            acc.z += v0.z * a0; acc.w += v0.w * a0;
        }
    }
    float ss = acc.x * acc.x + acc.y * acc.y + acc.z * acc.z + acc.w * acc.w;
    ss += __shfl_xor_sync(0xffffffffu, ss, 16);
    ss += __shfl_xor_sync(0xffffffffu, ss, 8);
    ss += __shfl_xor_sync(0xffffffffu, ss, 4);
    ss += __shfl_xor_sync(0xffffffffu, ss, 2);
    ss += __shfl_xor_sync(0xffffffffu, ss, 1);
    float ni = 1.0f / fmaxf(sqrtf(ss), 1e-12f);
    float4 o = make_float4(acc.x * ni, acc.y * ni, acc.z * ni, acc.w * ni);
    if (cur_out) ((uint2*)(cur_out + (size_t)gw * C))[lane] = pack4(o.x, o.y, o.z, o.w);
    const float* rib = (gw < split) ? ri0 + (size_t)gw * C : ri1 + (size_t)(gw - split) * C;
    float4 r = __ldg((const float4*)rib + lane);
    r.x += o.x; r.y += o.y; r.z += o.z; r.w += o.w;
    ((float4*)(res + (size_t)gw * C))[lane] = r;
}

// ================= interact-mat aggregation (CSR, fp16 gather, fused norm+res) ==========
__global__ __launch_bounds__(256) void user_agg_csr(
    const int* __restrict__ off, const int2* __restrict__ srt,
    const __half* __restrict__ src, float* __restrict__ res,
    const float* __restrict__ res_init, int n)
{
    int gw = (blockIdx.x * 256 + threadIdx.x) >> 5, lane = threadIdx.x & 31;
    if (gw >= n) return;
    int base = off[gw], end = off[gw + 1];
    float4 acc = make_float4(0.f, 0.f, 0.f, 0.f);
    for (int e0 = base; e0 < end; e0 += 32) {
        int cnt = min(32, end - e0);
        int mc = 0; float mv = 0.f;
        if (lane < cnt) { int2 p = __ldg(srt + e0 + lane); mc = p.x; mv = __int_as_float(p.y); }
        int j = 0;
        for (; j + 4 <= cnt; j += 4) {
            int c0 = __shfl_sync(0xffffffffu, mc, j + 0);
            int c1 = __shfl_sync(0xffffffffu, mc, j + 1);
            int c2 = __shfl_sync(0xffffffffu, mc, j + 2);
            int c3 = __shfl_sync(0xffffffffu, mc, j + 3);
            float a0 = __shfl_sync(0xffffffffu, mv, j + 0);
            float a1 = __shfl_sync(0xffffffffu, mv, j + 1);
            float a2 = __shfl_sync(0xffffffffu, mv, j + 2);
            float a3 = __shfl_sync(0xffffffffu, mv, j + 3);
            float4 v0 = unpack4(__ldg((const uint2*)(src + (size_t)c0 * C) + lane));
            float4 v1 = unpack4(__ldg((const uint2*)(src + (size_t)c1 * C) + lane));
            float4 v2 = unpack4(__ldg((const uint2*)(src + (size_t)c2 * C) + lane));
            float4 v3 = unpack4(__ldg((const uint2*)(src + (size_t)c3 * C) + lane));
            acc.x += v0.x * a0 + v1.x * a1 + v2.x * a2 + v3.x * a3;
            acc.y += v0.y * a0 + v1.y * a1 + v2.y * a2 + v3.y * a3;
            acc.z += v0.z * a0 + v1.z * a1 + v2.z * a2 + v3.z * a3;
            acc.w += v0.w * a0 + v1.w * a1 + v2.w * a2 + v3.w * a3;
        }
        for (; j < cnt; j++) {
            int c0 = __shfl_sync(0xffffffffu, mc, j);
            float a0 = __shfl_sync(0xffffffffu, mv, j);
            float4 v0 = unpack4(__ldg((const uint2*)(src + (size_t)c0 * C) + lane));
            acc.x += v0.x * a0; acc.y += v0.y * a0;
            acc.z += v0.z * a0; acc.w += v0.w * a0;
        }
    }
    float ss = acc.x * acc.x + acc.y * acc.y + acc.z * acc.z + acc.w * acc.w;
    ss += __shfl_xor_sync(0xffffffffu, ss, 16);
    ss += __shfl_xor_sync(0xffffffffu, ss, 8);
    ss += __shfl_xor_sync(0xffffffffu, ss, 4);
    ss += __shfl_xor_sync(0xffffffffu, ss, 2);
    ss += __shfl_xor_sync(0xffffffffu, ss, 1);
    float ni = 1.0f / fmaxf(sqrtf(ss), 1e-12f);
    float4 o = make_float4(acc.x * ni, acc.y * ni, acc.z * ni, acc.w * ni);
    float4 r = __ldg((const float4*)(res_init + (size_t)gw * C) + lane);
    r.x += o.x; r.y += o.y; r.z += o.z; r.w += o.w;
    ((float4*)(res + (size_t)gw * C))[lane] = r;
}

// ================= host launcher =================
extern "C" void kernel_launch(void* const* d_in, const int* in_sizes, int n_in,
                              void* d_out, int out_size)
{
    const float* user   = (const float*)d_in[0];
    const float* ent    = (const float*)d_in[1];
    const int*   eidx   = (const int*)  d_in[2];
    const int*   etype  = (const int*)  d_in[3];
    const int*   exidx  = (const int*)  d_in[4];
    const int*   irows  = (const int*)  d_in[6];
    const int*   icols  = (const int*)  d_in[7];
    const float* ivals  = (const float*)d_in[8];
    const float* weight = (const float*)d_in[9];
    const float* WQ     = (const float*)d_in[11];
    const float* WK     = (const float*)d_in[12];

    int n_users = in_sizes[0] / C;
    int n_ent   = in_sizes[1] / C;
    int n_nodes = n_users + n_ent;
    int E   = in_sizes[3];
    int EX  = in_sizes[5];
    int NNZ = in_sizes[6];

    size_t UB = (size_t)n_users * C;
    size_t EB = (size_t)n_ent * C;

    float *augp;
    __half *hNodeA, *hNodeB, *hEntB, *hEntM, *hQ, *hK, *WT;
    float2* exps;
    int *srt_e, *srt_x, *off3, *cur3, *deg3, *part3;
    int2* srt_i;
    cudaGetSymbolAddress((void**)&hNodeA, g_hNodeA);
    cudaGetSymbolAddress((void**)&hNodeB, g_hNodeB);
    cudaGetSymbolAddress((void**)&hEntB,  g_hEntB);
    cudaGetSymbolAddress((void**)&hEntM,  g_hEntM);
    cudaGetSymbolAddress((void**)&hQ,     g_hQ);
    cudaGetSymbolAddress((void**)&hK,     g_hK);
    cudaGetSymbolAddress((void**)&WT,     g_WT);
    cudaGetSymbolAddress((void**)&augp,   g_aug);
    cudaGetSymbolAddress((void**)&exps,   g_exps);
    cudaGetSymbolAddress((void**)&srt_e,  g_srt_ent);
    cudaGetSymbolAddress((void**)&srt_x,  g_srt_x);
    cudaGetSymbolAddress((void**)&srt_i,  g_srt_i);
    cudaGetSymbolAddress((void**)&off3,   g_off3);
    cudaGetSymbolAddress((void**)&cur3,   g_cur3);
    cudaGetSymbolAddress((void**)&deg3,   g_deg3);
    cudaGetSymbolAddress((void**)&part3,  g_part3);

    int* off_e = off3;
    int* off_n = off3 + OFFS;
    int* off_u = off3 + 2 * OFFS;

    float* out = (float*)d_out;
    float* user_res = out;              // [n_users, C]
    float* ent_res  = out + UB;         // [n_ent, C]
    float* node_res = out + UB + EB;    // [n_nodes, C]

    const int* eh = eidx;          const int* et = eidx + E;
    const int* xh = exidx;         const int* xt = exidx + EX;

    // fp16 concat of node embeddings (entity half at hNodeA + UB)
    {
        size_t n4 = (size_t)n_nodes * 32;
        conv2<<<(unsigned)((n4 + 255) / 256), 256>>>(user, ent, UB / 4, n4, hNodeA);
    }
    wt_conv<<<(2 * C * C + 255) / 256, 256>>>(WQ, WK, WT);

    // ---- batched CSR build for the 3 graphs ----
    cudaMemsetAsync(deg3, 0, 3 * DEGS * 4);
    {
        int tot = E + EX + NNZ;
        hist3<<<(tot + 255) / 256, 256>>>(eh, E, xh, EX, irows, NNZ, deg3);
    }
    {
        dim3 g((n_nodes + 1023) >> 10, 3);
        scan_block3<<<g, 1024>>>(deg3, off3, part3, n_ent, n_nodes, n_users);
        scan_part3<<<1, 96>>>(part3);
        dim3 g2((n_nodes + 256) / 256 + 1, 3);
        add_offs3<<<g2, 256>>>(off3, part3, n_ent, n_nodes, n_users);
    }
    cudaMemcpyAsync(cur3, off3, 3 * OFFS * 4, cudaMemcpyDeviceToDevice);
    {
        int tot = E + EX + NNZ;
        scat3<<<(tot + 255) / 256, 256>>>(eh, et, etype, E, xh, xt, EX,
                                          irows, icols, ivals, NNZ,
                                          cur3, srt_e, srt_x, srt_i);
    }

    // ---- attention weights (once; reused both hops) ----
    {
        int smem = (SB_H + SA_H) * 2;
        cudaFuncSetAttribute(qk_mma, cudaFuncAttributeMaxDynamicSharedMemorySize, smem);
        qk_mma<<<(n_nodes + 63) / 64, 256, smem>>>(hNodeA, WT, hQ, hK, n_nodes);
    }
    attn_csr<<<(n_nodes * 32 + 255) / 256, 256>>>(off_n, srt_x, hQ, hK, exps, augp, n_nodes);

    // ---- hop 1 ----
    ent_agg_csr<<<(n_ent * 32 + 255) / 256, 256>>>(
        off_e, srt_e, hNodeA + UB, weight, hEntM, hEntB, ent_res, ent, n_ent);
    user_agg_csr<<<(n_users * 32 + 255) / 256, 256>>>(
        off_u, srt_i, hEntM, user_res, user, n_users);
    node_agg_csr<<<(n_nodes * 32 + 255) / 256, 256>>>(
        off_n, srt_x, augp, hNodeA, hNodeB, node_res, user, ent, n_users, n_nodes);

    // ---- hop 2 ----
    ent_agg_csr<<<(n_ent * 32 + 255) / 256, 256>>>(
        off_e, srt_e, hEntB, weight, hEntM, (__half*)0, ent_res, ent_res, n_ent);
    user_agg_csr<<<(n_users * 32 + 255) / 256, 256>>>(
        off_u, srt_i, hEntM, user_res, user_res, n_users);
    node_agg_csr<<<(n_nodes * 32 + 255) / 256, 256>>>(
        off_n, srt_x, augp, hNodeB, (__half*)0, node_res, node_res, node_res, n_nodes, n_nodes);
}